// round 11
// baseline (speedup 1.0000x reference)
#include <cuda_runtime.h>
#include <math.h>
#include <stdint.h>

#define NN 50000
#define NE 400000
#define NBLK 391                 // ceil(50000/128)

// ---------------- scratch (device globals; allocation-free) ----------------
__device__ __align__(16) float g_a_hi[NN * 256];     // activation tf32-hi, stride 256
__device__ __align__(16) float g_a_lo[NN * 256];     // activation tf32-lo
__device__ __align__(16) float g_h[NN * 256];        // GEMM out (fp32), stride 256
// total W^T split footprint: e-tower 164864 + v-tower 65536 = 230400 floats
__device__ __align__(16) float g_wt_hi[231424];      // all layers' W^T tf32-hi (+pad)
__device__ __align__(16) float g_wt_lo[231424];
__device__ float g_dinv[NN];
__device__ int   g_deg[NN];
__device__ int2  g_edges[NE];
__device__ int   g_rowptr[NN + 1];
__device__ int   g_cursor[NN];
__device__ int   g_col[NE];
__device__ int   g_is64;

// ---------------- helpers ----------------
__device__ __forceinline__ float tf32r(float x) {
    uint32_t u;
    asm("cvt.rna.tf32.f32 %0, %1;" : "=r"(u) : "f"(x));
    return __uint_as_float(u);
}
__device__ __forceinline__ void mma8(float* c, const uint32_t* a, const uint32_t* b) {
    asm volatile(
        "mma.sync.aligned.m16n8k8.row.col.f32.tf32.tf32.f32 "
        "{%0,%1,%2,%3}, {%4,%5,%6,%7}, {%8,%9}, {%0,%1,%2,%3};"
        : "+f"(c[0]), "+f"(c[1]), "+f"(c[2]), "+f"(c[3])
        : "r"(a[0]), "r"(a[1]), "r"(a[2]), "r"(a[3]), "r"(b[0]), "r"(b[1]));
}
__device__ __forceinline__ void cpa16(uint32_t s, const void* g) {
    asm volatile("cp.async.ca.shared.global [%0], [%1], 16;" :: "r"(s), "l"(g));
}
#define CP_COMMIT() asm volatile("cp.async.commit_group;" ::: "memory")
#define CP_WAIT1()  asm volatile("cp.async.wait_group 1;" ::: "memory")

// ---------------- edge dtype sniff + decode ----------------
__global__ void k_detect(const int* __restrict__ e) {
    int all0 = 1;
    for (int i = 0; i < 128; i++)
        if (e[2 * i + 1] != 0) { all0 = 0; break; }
    g_is64 = all0;
}

__global__ void k_prep(const int* __restrict__ e) {
    int i = blockIdx.x * 256 + threadIdx.x;
    if (i >= NE) return;
    int s, d;
    if (g_is64) { s = e[2 * i]; d = e[2 * (NE + i)]; }
    else        { s = e[i];     d = e[NE + i]; }
    s = min(max(s, 0), NN - 1);
    d = min(max(d, 0), NN - 1);
    g_edges[i] = make_int2(s, d);
}

// ---------------- degree / dinv / CSR build ----------------
__global__ void k_zero_deg() {
    int i = blockIdx.x * 256 + threadIdx.x;
    if (i < NN) g_deg[i] = 0;
}
__global__ void k_deg() {
    int i = blockIdx.x * 256 + threadIdx.x;
    if (i < NE) atomicAdd(&g_deg[g_edges[i].y], 1);
}
__global__ void k_dinv() {
    int i = blockIdx.x * 256 + threadIdx.x;
    if (i < NN) g_dinv[i] = rsqrtf((float)(g_deg[i] + 1));
}

__global__ __launch_bounds__(1024) void k_scan() {
    __shared__ int ssum[1024];
    const int t = threadIdx.x;
    const int CH = (NN + 1023) / 1024;
    int beg = t * CH;
    int end = min(beg + CH, NN);
    int s = 0;
    for (int i = beg; i < end; i++) s += g_deg[i];
    ssum[t] = s;
    __syncthreads();
    for (int off = 1; off < 1024; off <<= 1) {
        int v = ssum[t];
        int u = (t >= off) ? ssum[t - off] : 0;
        __syncthreads();
        ssum[t] = v + u;
        __syncthreads();
    }
    int run = (t == 0) ? 0 : ssum[t - 1];
    for (int i = beg; i < end; i++) {
        g_rowptr[i] = run;
        g_cursor[i] = run;
        run += g_deg[i];
    }
    if (t == 1023) g_rowptr[NN] = run;
}

__global__ void k_place() {
    int i = blockIdx.x * 256 + threadIdx.x;
    if (i >= NE) return;
    int2 sd = g_edges[i];
    int pos = atomicAdd(&g_cursor[sd.y], 1);
    g_col[pos] = sd.x;
}

// -------- x split --------------------------------------------------
__global__ void k_xsplit(const float* __restrict__ x) {
    int i = blockIdx.x * 256 + threadIdx.x;      // quad index
    if (i >= NN * 32) return;
    int n = i >> 5, q = (i & 31) << 2;
    float4 v = *(const float4*)(x + (size_t)n * 128 + q);
    float4 hi, lo;
    hi.x = tf32r(v.x); lo.x = tf32r(v.x - hi.x);
    hi.y = tf32r(v.y); lo.y = tf32r(v.y - hi.y);
    hi.z = tf32r(v.z); lo.z = tf32r(v.z - hi.z);
    hi.w = tf32r(v.w); lo.w = tf32r(v.w - hi.w);
    *(float4*)(g_a_hi + (size_t)n * 256 + q) = hi;
    *(float4*)(g_a_lo + (size_t)n * 256 + q) = lo;
}

// -------- all-layer W prep: transpose + tf32 split + zero-pad ---------------
struct WP8 {
    const float* W[8];
    int K[8], C[8], Kpad[8], Np[8], off[8];
};
__global__ void k_wprep8(WP8 p) {
    int l = blockIdx.y;
    int i = blockIdx.x * 256 + threadIdx.x;
    if (i >= p.Np[l] * p.Kpad[l]) return;
    int n = i / p.Kpad[l], k = i % p.Kpad[l];
    float w = (n < p.C[l] && k < p.K[l]) ? p.W[l][(size_t)k * p.C[l] + n] : 0.f;
    float hi = tf32r(w);
    g_wt_hi[p.off[l] + i] = hi;
    g_wt_lo[p.off[l] + i] = tf32r(w - hi);
}

// -------- cp.async double-buffered tf32 GEMM (3x split) -> fp32 H -----------
// tile 128 x 64 x 16; 8 warps (4M x 2N); A from g_a_hi/lo (stride 256).
#define STG 7680
#define SMEM_TC (2 * STG * 4)

__global__ __launch_bounds__(256) void k_gemm_tc(int woff, int ldb, int Kpad, int C)
{
    extern __shared__ float sm[];
    const int tid = threadIdx.x;
    const int wid = tid >> 5, lid = tid & 31;
    const int warpM = wid & 3, warpN = wid >> 2;
    const int g = lid >> 2, tg = lid & 3;
    const int row0 = blockIdx.y * 128;
    const int col0 = blockIdx.x * 64;
    const uint32_t sb = (uint32_t)__cvta_generic_to_shared(sm);

    const float* aSrc[4]; uint32_t aDst[4];
    const float* bSrc[2]; uint32_t bDst[2];
#pragma unroll
    for (int i = 0; i < 4; i++) {
        int l = tid + i * 256;
        int r = (l & 511) >> 2, q = (l & 3) << 2;
        int gr = row0 + r; if (gr > NN - 1) gr = NN - 1;
        aSrc[i] = ((l < 512) ? g_a_hi : g_a_lo) + (size_t)gr * 256 + q;
        aDst[i] = (uint32_t)(((l < 512) ? 0 : 2560) + r * 20 + q) * 4;
    }
#pragma unroll
    for (int i = 0; i < 2; i++) {
        int l = tid + i * 256;
        int r = (l & 255) >> 2, q = (l & 3) << 2;
        bSrc[i] = ((l < 256) ? g_wt_hi : g_wt_lo) + woff + (size_t)(col0 + r) * ldb + q;
        bDst[i] = (uint32_t)(((l < 256) ? 5120 : 6400) + r * 20 + q) * 4;
    }

    float acc[2][4][4];
#pragma unroll
    for (int mt = 0; mt < 2; mt++)
#pragma unroll
        for (int nt = 0; nt < 4; nt++)
#pragma unroll
            for (int j = 0; j < 4; j++) acc[mt][nt][j] = 0.f;

    const int nch = Kpad >> 4;
#pragma unroll
    for (int i = 0; i < 4; i++) cpa16(sb + aDst[i], aSrc[i]);
#pragma unroll
    for (int i = 0; i < 2; i++) cpa16(sb + bDst[i], bSrc[i]);
    CP_COMMIT();

    for (int ch = 0; ch < nch; ch++) {
        if (ch + 1 < nch) {
            const uint32_t nOff = (uint32_t)((ch + 1) & 1) * (STG * 4);
            const int kt = (ch + 1) << 4;
#pragma unroll
            for (int i = 0; i < 4; i++) cpa16(sb + nOff + aDst[i], aSrc[i] + kt);
#pragma unroll
            for (int i = 0; i < 2; i++) cpa16(sb + nOff + bDst[i], bSrc[i] + kt);
        }
        CP_COMMIT();
        CP_WAIT1();
        __syncthreads();

        const float* As_hi = sm + (ch & 1) * STG;
        const float* As_lo = As_hi + 2560;
        const float* Bs_hi = As_hi + 5120;
        const float* Bs_lo = As_hi + 6400;

#pragma unroll
        for (int ks = 0; ks < 2; ks++) {
            const int kk = ks * 8;
            uint32_t ah[2][4], al[2][4], bh[4][2], bl[4][2];
#pragma unroll
            for (int mt = 0; mt < 2; mt++) {
                int rb = warpM * 32 + mt * 16;
                ah[mt][0] = __float_as_uint(As_hi[(rb + g)     * 20 + kk + tg]);
                ah[mt][1] = __float_as_uint(As_hi[(rb + g + 8) * 20 + kk + tg]);
                ah[mt][2] = __float_as_uint(As_hi[(rb + g)     * 20 + kk + tg + 4]);
                ah[mt][3] = __float_as_uint(As_hi[(rb + g + 8) * 20 + kk + tg + 4]);
                al[mt][0] = __float_as_uint(As_lo[(rb + g)     * 20 + kk + tg]);
                al[mt][1] = __float_as_uint(As_lo[(rb + g + 8) * 20 + kk + tg]);
                al[mt][2] = __float_as_uint(As_lo[(rb + g)     * 20 + kk + tg + 4]);
                al[mt][3] = __float_as_uint(As_lo[(rb + g + 8) * 20 + kk + tg + 4]);
            }
#pragma unroll
            for (int nt = 0; nt < 4; nt++) {
                int cb = warpN * 32 + nt * 8;
                bh[nt][0] = __float_as_uint(Bs_hi[(cb + g) * 20 + kk + tg]);
                bh[nt][1] = __float_as_uint(Bs_hi[(cb + g) * 20 + kk + tg + 4]);
                bl[nt][0] = __float_as_uint(Bs_lo[(cb + g) * 20 + kk + tg]);
                bl[nt][1] = __float_as_uint(Bs_lo[(cb + g) * 20 + kk + tg + 4]);
            }
#pragma unroll
            for (int mt = 0; mt < 2; mt++)
#pragma unroll
                for (int nt = 0; nt < 4; nt++) {
                    mma8(acc[mt][nt], ah[mt], bh[nt]);
                    mma8(acc[mt][nt], ah[mt], bl[nt]);
                    mma8(acc[mt][nt], al[mt], bh[nt]);
                }
        }
        __syncthreads();
    }

    // epilogue: * dinv -> g_h (stride 256); pad cols zero
#pragma unroll
    for (int mt = 0; mt < 2; mt++) {
#pragma unroll
        for (int half = 0; half < 2; half++) {
            int r = row0 + warpM * 32 + mt * 16 + g + half * 8;
            if (r >= NN) continue;
            float dv = g_dinv[r];
#pragma unroll
            for (int nt = 0; nt < 4; nt++) {
                int c = col0 + warpN * 32 + nt * 8 + tg * 2;
                float v0 = (c < C)     ? acc[mt][nt][half * 2 + 0] * dv : 0.f;
                float v1 = (c + 1 < C) ? acc[mt][nt][half * 2 + 1] * dv : 0.f;
                g_h[(size_t)r * 256 + c]     = v0;
                g_h[(size_t)r * 256 + c + 1] = v1;
            }
        }
    }
}

// -------- warp-per-node gather + self-loop + bias + act + tf32 split --------
// 4 warps/block, warp = 1 node, lane = 8 fp32 channels (two float4 loads).
__global__ __launch_bounds__(128) void k_gatherw(
    const float* __restrict__ bias, float* __restrict__ outExt,
    int isFinal, int C, int CpadOut, int act)
{
    const int lane = threadIdx.x & 31;
    const int d = blockIdx.x * 4 + (threadIdx.x >> 5);
    const int beg = g_rowptr[d];
    const int deg = g_rowptr[d + 1] - beg;
    const int ch = lane << 3;              // 8 channels per lane
    const bool act8 = (ch < C);

    float s[8];
#pragma unroll
    for (int j = 0; j < 8; j++) s[j] = 0.f;

    for (int done = 0; done < deg; done += 32) {
        int chunk = min(deg - done, 32);
        int idx = 0;
        if (lane < chunk) idx = g_col[beg + done + lane];
        int i = 0;
        for (; i + 4 <= chunk; i += 4) {
            int n0 = __shfl_sync(0xffffffffu, idx, i);
            int n1 = __shfl_sync(0xffffffffu, idx, i + 1);
            int n2 = __shfl_sync(0xffffffffu, idx, i + 2);
            int n3 = __shfl_sync(0xffffffffu, idx, i + 3);
            if (act8) {
                const float* p0 = g_h + (size_t)n0 * 256 + ch;
                const float* p1 = g_h + (size_t)n1 * 256 + ch;
                const float* p2 = g_h + (size_t)n2 * 256 + ch;
                const float* p3 = g_h + (size_t)n3 * 256 + ch;
                float4 a0 = *(const float4*)p0, b0 = *(const float4*)(p0 + 4);
                float4 a1 = *(const float4*)p1, b1 = *(const float4*)(p1 + 4);
                float4 a2 = *(const float4*)p2, b2 = *(const float4*)(p2 + 4);
                float4 a3 = *(const float4*)p3, b3 = *(const float4*)(p3 + 4);
                s[0] += a0.x + a1.x + a2.x + a3.x;
                s[1] += a0.y + a1.y + a2.y + a3.y;
                s[2] += a0.z + a1.z + a2.z + a3.z;
                s[3] += a0.w + a1.w + a2.w + a3.w;
                s[4] += b0.x + b1.x + b2.x + b3.x;
                s[5] += b0.y + b1.y + b2.y + b3.y;
                s[6] += b0.z + b1.z + b2.z + b3.z;
                s[7] += b0.w + b1.w + b2.w + b3.w;
            }
        }
        for (; i < chunk; i++) {
            int n0 = __shfl_sync(0xffffffffu, idx, i);
            if (act8) {
                const float* p0 = g_h + (size_t)n0 * 256 + ch;
                float4 a0 = *(const float4*)p0, b0 = *(const float4*)(p0 + 4);
                s[0] += a0.x; s[1] += a0.y; s[2] += a0.z; s[3] += a0.w;
                s[4] += b0.x; s[5] += b0.y; s[6] += b0.z; s[7] += b0.w;
            }
        }
    }

    if (ch >= CpadOut) return;
    const float dv = g_dinv[d];
    float val[8];
#pragma unroll
    for (int j = 0; j < 8; j++) val[j] = 0.f;
    if (act8) {
        const float* hp = g_h + (size_t)d * 256 + ch;
        float4 ha = *(const float4*)hp, hb = *(const float4*)(hp + 4);
        float hs[8] = {ha.x, ha.y, ha.z, ha.w, hb.x, hb.y, hb.z, hb.w};
#pragma unroll
        for (int j = 0; j < 8; j++) {
            int c = ch + j;
            if (c < C) {
                float v = (s[j] + hs[j]) * dv + bias[c];
                if (act == 0) v = fmaxf(v, 0.f);
                else          v = 1.f / (1.f + expf(-v));
                val[j] = v;
            }
        }
    }
    if (isFinal) {
        if (ch < C) {
            *(float4*)(outExt + (size_t)d * C + ch) =
                make_float4(val[0], val[1], val[2], val[3]);
            *(float4*)(outExt + (size_t)d * C + ch + 4) =
                make_float4(val[4], val[5], val[6], val[7]);
        }
    } else {
        float hi[8], lo[8];
#pragma unroll
        for (int j = 0; j < 8; j++) {
            hi[j] = tf32r(val[j]);
            lo[j] = tf32r(val[j] - hi[j]);
        }
        *(float4*)(g_a_hi + (size_t)d * 256 + ch)     = make_float4(hi[0], hi[1], hi[2], hi[3]);
        *(float4*)(g_a_hi + (size_t)d * 256 + ch + 4) = make_float4(hi[4], hi[5], hi[6], hi[7]);
        *(float4*)(g_a_lo + (size_t)d * 256 + ch)     = make_float4(lo[0], lo[1], lo[2], lo[3]);
        *(float4*)(g_a_lo + (size_t)d * 256 + ch + 4) = make_float4(lo[4], lo[5], lo[6], lo[7]);
    }
}

// ---------------------------------------------------------------------------
static void run_tower(const float* x,
                      const float* const* b, const int* Kd, const int* Cd,
                      const int* woff, float* finalOut)
{
    k_xsplit<<<(NN * 32 + 255) / 256, 256>>>(x);
    for (int l = 0; l < 4; l++) {
        int K = Kd[l], C = Cd[l];
        int Kpad = (K + 15) & ~15;
        int Npad64 = (C + 63) & ~63;
        int CpadOut = (C + 31) & ~31;

        dim3 gg(Npad64 / 64, NBLK);
        k_gemm_tc<<<gg, 256, SMEM_TC>>>(woff[l], Kpad, Kpad, C);
        k_gatherw<<<NN / 4, 128>>>(b[l], finalOut, (l == 3) ? 1 : 0,
                                   C, CpadOut, (l == 3) ? 1 : 0);
    }
}

extern "C" void kernel_launch(void* const* d_in, const int* in_sizes, int n_in,
                              void* d_out, int out_size)
{
    const float* x = (const float*)d_in[0];
    const int* ei = (const int*)d_in[1];

    const float* We[4] = {(const float*)d_in[2], (const float*)d_in[4],
                          (const float*)d_in[6], (const float*)d_in[8]};
    const float* be[4] = {(const float*)d_in[3], (const float*)d_in[5],
                          (const float*)d_in[7], (const float*)d_in[9]};
    const float* Wn[4] = {(const float*)d_in[10], (const float*)d_in[12],
                          (const float*)d_in[14], (const float*)d_in[16]};
    const float* bn[4] = {(const float*)d_in[11], (const float*)d_in[13],
                          (const float*)d_in[15], (const float*)d_in[17]};

    float* out = (float*)d_out;

    cudaFuncSetAttribute(k_gemm_tc, cudaFuncAttributeMaxDynamicSharedMemorySize,
                         SMEM_TC);

    static const int Ke[4] = {128, 166, 192, 218};
    static const int Ce[4] = {166, 192, 218, 256};
    static const int Kn[4] = {128, 128, 128, 128};
    static const int Cn[4] = {128, 128, 128, 128};

    // build combined W-prep descriptor (layers: e0..e3, v0..v3)
    WP8 p;
    int offE[4], offN[4];
    int off = 0, maxElems = 0;
    for (int l = 0; l < 8; l++) {
        int K = (l < 4) ? Ke[l] : Kn[l - 4];
        int C = (l < 4) ? Ce[l] : Cn[l - 4];
        p.W[l] = (l < 4) ? We[l] : Wn[l - 4];
        p.K[l] = K; p.C[l] = C;
        p.Kpad[l] = (K + 15) & ~15;
        p.Np[l]   = (C + 63) & ~63;
        p.off[l]  = off;
        if (l < 4) offE[l] = off; else offN[l - 4] = off;
        int elems = p.Kpad[l] * p.Np[l];
        if (elems > maxElems) maxElems = elems;
        off += elems;
    }
    // off == 230400 total; g_wt_hi/lo sized 231424 (verified >= off)

    // edge decode + graph normalization + CSR (shared by both towers)
    k_detect<<<1, 1>>>(ei);
    k_prep<<<(NE + 255) / 256, 256>>>(ei);
    k_zero_deg<<<(NN + 255) / 256, 256>>>();
    k_deg<<<(NE + 255) / 256, 256>>>();
    k_dinv<<<(NN + 255) / 256, 256>>>();
    k_scan<<<1, 1024>>>();
    k_place<<<(NE + 255) / 256, 256>>>();

    dim3 wg((maxElems + 255) / 256, 8);
    k_wprep8<<<wg, 256>>>(p);

    // e tower -> out[0 : NN*256]
    run_tower(x, be, Ke, Ce, offE, out);
    // v tower -> out[NN*256 : NN*256 + NN*128]
    run_tower(x, bn, Kn, Cn, offN, out + (size_t)NN * 256);
}

// round 12
// speedup vs baseline: 1.0485x; 1.0485x over previous
#include <cuda_runtime.h>
#include <math.h>
#include <stdint.h>

#define NN 50000
#define NE 400000
#define NBLK 391                 // ceil(50000/128)

// ---------------- scratch (device globals; allocation-free) ----------------
__device__ __align__(16) float g_a_hi[NN * 256];     // split AG (GEMM input), stride 256
__device__ __align__(16) float g_a_lo[NN * 256];
__device__ __align__(16) float g_ag0_hi[NN * 128];   // shared first-layer AG, stride 128
__device__ __align__(16) float g_ag0_lo[NN * 128];
__device__ __align__(16) float g_act[NN * 256];      // A' = act*dinv (fp32), stride 256
// total W^T split footprint: e-tower 164864 + v-tower 65536 = 230400 floats
__device__ __align__(16) float g_wt_hi[231424];
__device__ __align__(16) float g_wt_lo[231424];
__device__ float g_dinv[NN];
__device__ int   g_deg[NN];
__device__ int2  g_edges[NE];
__device__ int   g_rowptr[NN + 1];
__device__ int   g_cursor[NN];
__device__ int   g_col[NE];
__device__ int   g_is64;

// ---------------- helpers ----------------
__device__ __forceinline__ float tf32r(float x) {
    uint32_t u;
    asm("cvt.rna.tf32.f32 %0, %1;" : "=r"(u) : "f"(x));
    return __uint_as_float(u);
}
__device__ __forceinline__ void mma8(float* c, const uint32_t* a, const uint32_t* b) {
    asm volatile(
        "mma.sync.aligned.m16n8k8.row.col.f32.tf32.tf32.f32 "
        "{%0,%1,%2,%3}, {%4,%5,%6,%7}, {%8,%9}, {%0,%1,%2,%3};"
        : "+f"(c[0]), "+f"(c[1]), "+f"(c[2]), "+f"(c[3])
        : "r"(a[0]), "r"(a[1]), "r"(a[2]), "r"(a[3]), "r"(b[0]), "r"(b[1]));
}
__device__ __forceinline__ void cpa16(uint32_t s, const void* g) {
    asm volatile("cp.async.ca.shared.global [%0], [%1], 16;" :: "r"(s), "l"(g));
}
#define CP_COMMIT() asm volatile("cp.async.commit_group;" ::: "memory")
#define CP_WAIT1()  asm volatile("cp.async.wait_group 1;" ::: "memory")

// ---------------- edge dtype sniff + decode ----------------
__global__ void k_detect(const int* __restrict__ e) {
    int all0 = 1;
    for (int i = 0; i < 128; i++)
        if (e[2 * i + 1] != 0) { all0 = 0; break; }
    g_is64 = all0;
}

__global__ void k_prep(const int* __restrict__ e) {
    int i = blockIdx.x * 256 + threadIdx.x;
    if (i >= NE) return;
    int s, d;
    if (g_is64) { s = e[2 * i]; d = e[2 * (NE + i)]; }
    else        { s = e[i];     d = e[NE + i]; }
    s = min(max(s, 0), NN - 1);
    d = min(max(d, 0), NN - 1);
    g_edges[i] = make_int2(s, d);
}

// ---------------- degree / dinv / CSR build ----------------
__global__ void k_zero_deg() {
    int i = blockIdx.x * 256 + threadIdx.x;
    if (i < NN) g_deg[i] = 0;
}
__global__ void k_deg() {
    int i = blockIdx.x * 256 + threadIdx.x;
    if (i < NE) atomicAdd(&g_deg[g_edges[i].y], 1);
}
__global__ void k_dinv() {
    int i = blockIdx.x * 256 + threadIdx.x;
    if (i < NN) g_dinv[i] = rsqrtf((float)(g_deg[i] + 1));
}

__global__ __launch_bounds__(1024) void k_scan() {
    __shared__ int ssum[1024];
    const int t = threadIdx.x;
    const int CH = (NN + 1023) / 1024;
    int beg = t * CH;
    int end = min(beg + CH, NN);
    int s = 0;
    for (int i = beg; i < end; i++) s += g_deg[i];
    ssum[t] = s;
    __syncthreads();
    for (int off = 1; off < 1024; off <<= 1) {
        int v = ssum[t];
        int u = (t >= off) ? ssum[t - off] : 0;
        __syncthreads();
        ssum[t] = v + u;
        __syncthreads();
    }
    int run = (t == 0) ? 0 : ssum[t - 1];
    for (int i = beg; i < end; i++) {
        g_rowptr[i] = run;
        g_cursor[i] = run;
        run += g_deg[i];
    }
    if (t == 1023) g_rowptr[NN] = run;
}

__global__ void k_place() {
    int i = blockIdx.x * 256 + threadIdx.x;
    if (i >= NE) return;
    int2 sd = g_edges[i];
    int pos = atomicAdd(&g_cursor[sd.y], 1);
    g_col[pos] = sd.x;
}

// -------- A'_0 = x * dinv  (stride 256) -------------------------------------
__global__ void k_scale0(const float* __restrict__ x) {
    int i = blockIdx.x * 256 + threadIdx.x;      // quad index
    if (i >= NN * 32) return;
    int n = i >> 5, q = (i & 31) << 2;
    float dv = g_dinv[n];
    float4 v = *(const float4*)(x + (size_t)n * 128 + q);
    v.x *= dv; v.y *= dv; v.z *= dv; v.w *= dv;
    *(float4*)(g_act + (size_t)n * 256 + q) = v;
}

// -------- all-layer W prep: transpose + tf32 split + zero-pad ---------------
struct WP8 {
    const float* W[8];
    int K[8], C[8], Kpad[8], Np[8], off[8];
};
__global__ void k_wprep8(WP8 p) {
    int l = blockIdx.y;
    int i = blockIdx.x * 256 + threadIdx.x;
    if (i >= p.Np[l] * p.Kpad[l]) return;
    int n = i / p.Kpad[l], k = i % p.Kpad[l];
    float w = (n < p.C[l] && k < p.K[l]) ? p.W[l][(size_t)k * p.C[l] + n] : 0.f;
    float hi = tf32r(w);
    g_wt_hi[p.off[l] + i] = hi;
    g_wt_lo[p.off[l] + i] = tf32r(w - hi);
}

// -------- gather: AG[d] = dinv_d*(sum A'[s] + A'[d]), write tf32 split ------
// block = 64 threads, 1 node; thread = 4 channels. dstTag 0 -> g_ag0 (ld 128),
// 1 -> g_a (ld 256). Zero-fills cols [C, CpadW).
__global__ __launch_bounds__(64) void k_gather_split(int C, int CpadW, int dstTag)
{
    __shared__ int scol[64];
    const int d = blockIdx.x;
    const int beg = g_rowptr[d];
    const int deg = g_rowptr[d + 1] - beg;
    const int c4 = threadIdx.x << 2;

    float4 s = make_float4(0.f, 0.f, 0.f, 0.f);
    for (int done = 0; done < deg; done += 64) {
        int chunk = min(deg - done, 64);
        if (threadIdx.x < chunk) scol[threadIdx.x] = g_col[beg + done + threadIdx.x];
        __syncthreads();
        if (c4 < C) {
            for (int i = 0; i < chunk; i++) {
                float4 v = *(const float4*)(g_act + (size_t)scol[i] * 256 + c4);
                s.x += v.x; s.y += v.y; s.z += v.z; s.w += v.w;
            }
        }
        __syncthreads();
    }
    if (c4 >= CpadW) return;

    float val[4] = {0.f, 0.f, 0.f, 0.f};
    if (c4 < C) {
        const float dv = g_dinv[d];
        float4 h = *(const float4*)(g_act + (size_t)d * 256 + c4);
        val[0] = (s.x + h.x) * dv;
        val[1] = (s.y + h.y) * dv;
        val[2] = (s.z + h.z) * dv;
        val[3] = (s.w + h.w) * dv;
    }
    float hi[4], lo[4];
#pragma unroll
    for (int j = 0; j < 4; j++) {
        hi[j] = tf32r(val[j]);
        lo[j] = tf32r(val[j] - hi[j]);
    }
    if (dstTag == 0) {
        *(float4*)(g_ag0_hi + (size_t)d * 128 + c4) = make_float4(hi[0], hi[1], hi[2], hi[3]);
        *(float4*)(g_ag0_lo + (size_t)d * 128 + c4) = make_float4(lo[0], lo[1], lo[2], lo[3]);
    } else {
        *(float4*)(g_a_hi + (size_t)d * 256 + c4) = make_float4(hi[0], hi[1], hi[2], hi[3]);
        *(float4*)(g_a_lo + (size_t)d * 256 + c4) = make_float4(lo[0], lo[1], lo[2], lo[3]);
    }
}

// -------- cp.async double-buffered tf32 GEMM (3x split) ---------------------
// tile 128 x 64 x 16; 8 warps (4M x 2N). Epilogue: +bias, act,
// outMode 0: relu*dinv -> g_act (stride 256, pad zero); 1: sigmoid -> ext.
#define STG 7680
#define SMEM_TC (2 * STG * 4)

__global__ __launch_bounds__(256) void k_gemm_tc(
    int woff, int aTag, int lda, int Kpad, int C,
    const float* __restrict__ bias, float* __restrict__ extOut,
    int outMode, int ldo)
{
    extern __shared__ float sm[];
    const int tid = threadIdx.x;
    const int wid = tid >> 5, lid = tid & 31;
    const int warpM = wid & 3, warpN = wid >> 2;
    const int g = lid >> 2, tg = lid & 3;
    const int row0 = blockIdx.y * 128;
    const int col0 = blockIdx.x * 64;
    const uint32_t sb = (uint32_t)__cvta_generic_to_shared(sm);

    const float* baseHi = aTag ? g_a_hi : g_ag0_hi;
    const float* baseLo = aTag ? g_a_lo : g_ag0_lo;

    const float* aSrc[4]; uint32_t aDst[4];
    const float* bSrc[2]; uint32_t bDst[2];
#pragma unroll
    for (int i = 0; i < 4; i++) {
        int l = tid + i * 256;
        int r = (l & 511) >> 2, q = (l & 3) << 2;
        int gr = row0 + r; if (gr > NN - 1) gr = NN - 1;
        aSrc[i] = ((l < 512) ? baseHi : baseLo) + (size_t)gr * lda + q;
        aDst[i] = (uint32_t)(((l < 512) ? 0 : 2560) + r * 20 + q) * 4;
    }
#pragma unroll
    for (int i = 0; i < 2; i++) {
        int l = tid + i * 256;
        int r = (l & 255) >> 2, q = (l & 3) << 2;
        bSrc[i] = ((l < 256) ? g_wt_hi : g_wt_lo) + woff + (size_t)(col0 + r) * Kpad + q;
        bDst[i] = (uint32_t)(((l < 256) ? 5120 : 6400) + r * 20 + q) * 4;
    }

    float acc[2][4][4];
#pragma unroll
    for (int mt = 0; mt < 2; mt++)
#pragma unroll
        for (int nt = 0; nt < 4; nt++)
#pragma unroll
            for (int j = 0; j < 4; j++) acc[mt][nt][j] = 0.f;

    const int nch = Kpad >> 4;
#pragma unroll
    for (int i = 0; i < 4; i++) cpa16(sb + aDst[i], aSrc[i]);
#pragma unroll
    for (int i = 0; i < 2; i++) cpa16(sb + bDst[i], bSrc[i]);
    CP_COMMIT();

    for (int ch = 0; ch < nch; ch++) {
        if (ch + 1 < nch) {
            const uint32_t nOff = (uint32_t)((ch + 1) & 1) * (STG * 4);
            const int kt = (ch + 1) << 4;
#pragma unroll
            for (int i = 0; i < 4; i++) cpa16(sb + nOff + aDst[i], aSrc[i] + kt);
#pragma unroll
            for (int i = 0; i < 2; i++) cpa16(sb + nOff + bDst[i], bSrc[i] + kt);
        }
        CP_COMMIT();
        CP_WAIT1();
        __syncthreads();

        const float* As_hi = sm + (ch & 1) * STG;
        const float* As_lo = As_hi + 2560;
        const float* Bs_hi = As_hi + 5120;
        const float* Bs_lo = As_hi + 6400;

#pragma unroll
        for (int ks = 0; ks < 2; ks++) {
            const int kk = ks * 8;
            uint32_t ah[2][4], al[2][4], bh[4][2], bl[4][2];
#pragma unroll
            for (int mt = 0; mt < 2; mt++) {
                int rb = warpM * 32 + mt * 16;
                ah[mt][0] = __float_as_uint(As_hi[(rb + g)     * 20 + kk + tg]);
                ah[mt][1] = __float_as_uint(As_hi[(rb + g + 8) * 20 + kk + tg]);
                ah[mt][2] = __float_as_uint(As_hi[(rb + g)     * 20 + kk + tg + 4]);
                ah[mt][3] = __float_as_uint(As_hi[(rb + g + 8) * 20 + kk + tg + 4]);
                al[mt][0] = __float_as_uint(As_lo[(rb + g)     * 20 + kk + tg]);
                al[mt][1] = __float_as_uint(As_lo[(rb + g + 8) * 20 + kk + tg]);
                al[mt][2] = __float_as_uint(As_lo[(rb + g)     * 20 + kk + tg + 4]);
                al[mt][3] = __float_as_uint(As_lo[(rb + g + 8) * 20 + kk + tg + 4]);
            }
#pragma unroll
            for (int nt = 0; nt < 4; nt++) {
                int cb = warpN * 32 + nt * 8;
                bh[nt][0] = __float_as_uint(Bs_hi[(cb + g) * 20 + kk + tg]);
                bh[nt][1] = __float_as_uint(Bs_hi[(cb + g) * 20 + kk + tg + 4]);
                bl[nt][0] = __float_as_uint(Bs_lo[(cb + g) * 20 + kk + tg]);
                bl[nt][1] = __float_as_uint(Bs_lo[(cb + g) * 20 + kk + tg + 4]);
            }
#pragma unroll
            for (int mt = 0; mt < 2; mt++)
#pragma unroll
                for (int nt = 0; nt < 4; nt++) {
                    mma8(acc[mt][nt], ah[mt], bh[nt]);
                    mma8(acc[mt][nt], ah[mt], bl[nt]);
                    mma8(acc[mt][nt], al[mt], bh[nt]);
                }
        }
        __syncthreads();
    }

    // epilogue: +bias, activation, (dinv), store
#pragma unroll
    for (int mt = 0; mt < 2; mt++) {
#pragma unroll
        for (int half = 0; half < 2; half++) {
            int r = row0 + warpM * 32 + mt * 16 + g + half * 8;
            if (r >= NN) continue;
            float dv = g_dinv[r];
#pragma unroll
            for (int nt = 0; nt < 4; nt++) {
                int c = col0 + warpN * 32 + nt * 8 + tg * 2;
                float v0 = (c < C)     ? acc[mt][nt][half * 2 + 0] + bias[c]     : 0.f;
                float v1 = (c + 1 < C) ? acc[mt][nt][half * 2 + 1] + bias[c + 1] : 0.f;
                if (outMode == 0) {
                    // relu * dinv -> g_act (pad cols naturally become 0)
                    v0 = fmaxf(v0, 0.f) * dv;
                    v1 = fmaxf(v1, 0.f) * dv;
                    if (c >= C)     v0 = 0.f;
                    if (c + 1 >= C) v1 = 0.f;
                    g_act[(size_t)r * 256 + c]     = v0;
                    g_act[(size_t)r * 256 + c + 1] = v1;
                } else {
                    if (c < C)
                        extOut[(size_t)r * ldo + c] = 1.f / (1.f + expf(-v0));
                    if (c + 1 < C)
                        extOut[(size_t)r * ldo + c + 1] = 1.f / (1.f + expf(-v1));
                }
            }
        }
    }
}

// ---------------------------------------------------------------------------
// per-layer: AG = gather(A'); A'_next = act(AG @ W + b) [* dinv]
static void run_tower(const float* const* b, const int* Kd, const int* Cd,
                      const int* woff, float* finalOut, int ldoFinal)
{
    for (int l = 0; l < 4; l++) {
        int K = Kd[l], C = Cd[l];
        int Kpad = (K + 15) & ~15;
        int Npad64 = (C + 63) & ~63;

        if (l > 0) {
            int CpadW = (K + 15) & ~15;   // pad gather output to GEMM K-pad
            k_gather_split<<<NN, 64>>>(K, CpadW, 1);
        }
        int aTag = (l == 0) ? 0 : 1;
        int lda  = (l == 0) ? 128 : 256;
        dim3 gg(Npad64 / 64, NBLK);
        if (l < 3)
            k_gemm_tc<<<gg, 256, SMEM_TC>>>(woff[l], aTag, lda, Kpad, C,
                                            b[l], nullptr, 0, 0);
        else
            k_gemm_tc<<<gg, 256, SMEM_TC>>>(woff[l], aTag, lda, Kpad, C,
                                            b[l], finalOut, 1, ldoFinal);
    }
}

extern "C" void kernel_launch(void* const* d_in, const int* in_sizes, int n_in,
                              void* d_out, int out_size)
{
    const float* x = (const float*)d_in[0];
    const int* ei = (const int*)d_in[1];

    const float* We[4] = {(const float*)d_in[2], (const float*)d_in[4],
                          (const float*)d_in[6], (const float*)d_in[8]};
    const float* be[4] = {(const float*)d_in[3], (const float*)d_in[5],
                          (const float*)d_in[7], (const float*)d_in[9]};
    const float* Wn[4] = {(const float*)d_in[10], (const float*)d_in[12],
                          (const float*)d_in[14], (const float*)d_in[16]};
    const float* bn[4] = {(const float*)d_in[11], (const float*)d_in[13],
                          (const float*)d_in[15], (const float*)d_in[17]};

    float* out = (float*)d_out;

    cudaFuncSetAttribute(k_gemm_tc, cudaFuncAttributeMaxDynamicSharedMemorySize,
                         SMEM_TC);

    static const int Ke[4] = {128, 166, 192, 218};
    static const int Ce[4] = {166, 192, 218, 256};
    static const int Kn[4] = {128, 128, 128, 128};
    static const int Cn[4] = {128, 128, 128, 128};

    // combined W-prep descriptor (layers: e0..e3, v0..v3)
    WP8 p;
    int offE[4], offN[4];
    int off = 0, maxElems = 0;
    for (int l = 0; l < 8; l++) {
        int K = (l < 4) ? Ke[l] : Kn[l - 4];
        int C = (l < 4) ? Ce[l] : Cn[l - 4];
        p.W[l] = (l < 4) ? We[l] : Wn[l - 4];
        p.K[l] = K; p.C[l] = C;
        p.Kpad[l] = (K + 15) & ~15;
        p.Np[l]   = (C + 63) & ~63;
        p.off[l]  = off;
        if (l < 4) offE[l] = off; else offN[l - 4] = off;
        int elems = p.Kpad[l] * p.Np[l];
        if (elems > maxElems) maxElems = elems;
        off += elems;
    }
    // off == 230400 total; g_wt_hi/lo sized 231424

    // edge decode + graph normalization + CSR (shared by both towers)
    k_detect<<<1, 1>>>(ei);
    k_prep<<<(NE + 255) / 256, 256>>>(ei);
    k_zero_deg<<<(NN + 255) / 256, 256>>>();
    k_deg<<<(NE + 255) / 256, 256>>>();
    k_dinv<<<(NN + 255) / 256, 256>>>();
    k_scan<<<1, 1024>>>();
    k_place<<<(NE + 255) / 256, 256>>>();

    dim3 wg((maxElems + 255) / 256, 8);
    k_wprep8<<<wg, 256>>>(p);

    // shared first aggregation: A'_0 = x*dinv; AG0 = gather(A'_0) (128 ch)
    k_scale0<<<(NN * 32 + 255) / 256, 256>>>(x);
    k_gather_split<<<NN, 64>>>(128, 128, 0);

    // e tower -> out[0 : NN*256]
    run_tower(be, Ke, Ce, offE, out, 256);
    // v tower -> out[NN*256 : NN*256 + NN*128]
    run_tower(bn, Kn, Cn, offN, out + (size_t)NN * 256, 128);
}

// round 13
// speedup vs baseline: 1.0495x; 1.0009x over previous
#include <cuda_runtime.h>
#include <cuda_fp16.h>
#include <math.h>
#include <stdint.h>

#define NN 50000
#define NE 400000
#define NBLK 391                 // ceil(50000/128)

// ---------------- scratch (device globals; allocation-free) ----------------
__device__ __align__(16) float  g_a_hi[NN * 256];    // split AG (GEMM input), stride 256
__device__ __align__(16) float  g_a_lo[NN * 256];
__device__ __align__(16) float  g_ag0_hi[NN * 128];  // shared first-layer AG, stride 128
__device__ __align__(16) float  g_ag0_lo[NN * 128];
__device__ __align__(16) __half g_act[NN * 256];     // A' = act*dinv (fp16), stride 256
// total W^T split footprint: e-tower 164864 + v-tower 65536 = 230400 floats
__device__ __align__(16) float g_wt_hi[231424];
__device__ __align__(16) float g_wt_lo[231424];
__device__ float g_dinv[NN];
__device__ int   g_deg[NN];
__device__ int2  g_edges[NE];
__device__ int   g_rowptr[NN + 1];
__device__ int   g_cursor[NN];
__device__ int   g_col[NE];
__device__ int   g_is64;

// ---------------- helpers ----------------
__device__ __forceinline__ float tf32r(float x) {
    uint32_t u;
    asm("cvt.rna.tf32.f32 %0, %1;" : "=r"(u) : "f"(x));
    return __uint_as_float(u);
}
__device__ __forceinline__ void mma8(float* c, const uint32_t* a, const uint32_t* b) {
    asm volatile(
        "mma.sync.aligned.m16n8k8.row.col.f32.tf32.tf32.f32 "
        "{%0,%1,%2,%3}, {%4,%5,%6,%7}, {%8,%9}, {%0,%1,%2,%3};"
        : "+f"(c[0]), "+f"(c[1]), "+f"(c[2]), "+f"(c[3])
        : "r"(a[0]), "r"(a[1]), "r"(a[2]), "r"(a[3]), "r"(b[0]), "r"(b[1]));
}
__device__ __forceinline__ void cpa16(uint32_t s, const void* g) {
    asm volatile("cp.async.ca.shared.global [%0], [%1], 16;" :: "r"(s), "l"(g));
}
#define CP_COMMIT() asm volatile("cp.async.commit_group;" ::: "memory")
#define CP_WAIT1()  asm volatile("cp.async.wait_group 1;" ::: "memory")

// ---------------- edge dtype sniff + decode ----------------
__global__ void k_detect(const int* __restrict__ e) {
    int all0 = 1;
    for (int i = 0; i < 128; i++)
        if (e[2 * i + 1] != 0) { all0 = 0; break; }
    g_is64 = all0;
}

__global__ void k_prep(const int* __restrict__ e) {
    int i = blockIdx.x * 256 + threadIdx.x;
    if (i >= NE) return;
    int s, d;
    if (g_is64) { s = e[2 * i]; d = e[2 * (NE + i)]; }
    else        { s = e[i];     d = e[NE + i]; }
    s = min(max(s, 0), NN - 1);
    d = min(max(d, 0), NN - 1);
    g_edges[i] = make_int2(s, d);
}

// ---------------- degree / dinv / CSR build ----------------
__global__ void k_zero_deg() {
    int i = blockIdx.x * 256 + threadIdx.x;
    if (i < NN) g_deg[i] = 0;
}
__global__ void k_deg() {
    int i = blockIdx.x * 256 + threadIdx.x;
    if (i < NE) atomicAdd(&g_deg[g_edges[i].y], 1);
}
__global__ void k_dinv() {
    int i = blockIdx.x * 256 + threadIdx.x;
    if (i < NN) g_dinv[i] = rsqrtf((float)(g_deg[i] + 1));
}

__global__ __launch_bounds__(1024) void k_scan() {
    __shared__ int ssum[1024];
    const int t = threadIdx.x;
    const int CH = (NN + 1023) / 1024;
    int beg = t * CH;
    int end = min(beg + CH, NN);
    int s = 0;
    for (int i = beg; i < end; i++) s += g_deg[i];
    ssum[t] = s;
    __syncthreads();
    for (int off = 1; off < 1024; off <<= 1) {
        int v = ssum[t];
        int u = (t >= off) ? ssum[t - off] : 0;
        __syncthreads();
        ssum[t] = v + u;
        __syncthreads();
    }
    int run = (t == 0) ? 0 : ssum[t - 1];
    for (int i = beg; i < end; i++) {
        g_rowptr[i] = run;
        g_cursor[i] = run;
        run += g_deg[i];
    }
    if (t == 1023) g_rowptr[NN] = run;
}

__global__ void k_place() {
    int i = blockIdx.x * 256 + threadIdx.x;
    if (i >= NE) return;
    int2 sd = g_edges[i];
    int pos = atomicAdd(&g_cursor[sd.y], 1);
    g_col[pos] = sd.x;
}

// -------- A'_0 = x * dinv (fp16, stride 256) --------------------------------
__global__ void k_scale0(const float* __restrict__ x) {
    int i = blockIdx.x * 256 + threadIdx.x;      // quad index
    if (i >= NN * 32) return;
    int n = i >> 5, q = (i & 31) << 2;
    float dv = g_dinv[n];
    float4 v = *(const float4*)(x + (size_t)n * 128 + q);
    __half2 h0 = __floats2half2_rn(v.x * dv, v.y * dv);
    __half2 h1 = __floats2half2_rn(v.z * dv, v.w * dv);
    uint2 u;
    u.x = *(uint32_t*)&h0;
    u.y = *(uint32_t*)&h1;
    *(uint2*)(g_act + (size_t)n * 256 + q) = u;
}

// -------- all-layer W prep: transpose + tf32 split + zero-pad ---------------
struct WP8 {
    const float* W[8];
    int K[8], C[8], Kpad[8], Np[8], off[8];
};
__global__ void k_wprep8(WP8 p) {
    int l = blockIdx.y;
    int i = blockIdx.x * 256 + threadIdx.x;
    if (i >= p.Np[l] * p.Kpad[l]) return;
    int n = i / p.Kpad[l], k = i % p.Kpad[l];
    float w = (n < p.C[l] && k < p.K[l]) ? p.W[l][(size_t)k * p.C[l] + n] : 0.f;
    float hi = tf32r(w);
    g_wt_hi[p.off[l] + i] = hi;
    g_wt_lo[p.off[l] + i] = tf32r(w - hi);
}

// -------- gather: AG[d] = dinv_d*(sum A'[s] + A'[d]), write tf32 split ------
// block = 64 threads, 1 node; thread = 4 channels (one 8B fp16 load/neighbor).
// dstTag 0 -> g_ag0 (ld 128), 1 -> g_a (ld 256). Zero-fills [C, CpadW).
__global__ __launch_bounds__(64) void k_gather_split(int C, int CpadW, int dstTag)
{
    __shared__ int scol[64];
    const int d = blockIdx.x;
    const int beg = g_rowptr[d];
    const int deg = g_rowptr[d + 1] - beg;
    const int c4 = threadIdx.x << 2;

    float s0 = 0.f, s1 = 0.f, s2 = 0.f, s3 = 0.f;
    for (int done = 0; done < deg; done += 64) {
        int chunk = min(deg - done, 64);
        if (threadIdx.x < chunk) scol[threadIdx.x] = g_col[beg + done + threadIdx.x];
        __syncthreads();
        if (c4 < C) {
            for (int i = 0; i < chunk; i++) {
                uint2 u = *(const uint2*)(g_act + (size_t)scol[i] * 256 + c4);
                float2 f0 = __half22float2(*(__half2*)&u.x);
                float2 f1 = __half22float2(*(__half2*)&u.y);
                s0 += f0.x; s1 += f0.y; s2 += f1.x; s3 += f1.y;
            }
        }
        __syncthreads();
    }
    if (c4 >= CpadW) return;

    float val[4] = {0.f, 0.f, 0.f, 0.f};
    if (c4 < C) {
        const float dv = g_dinv[d];
        uint2 u = *(const uint2*)(g_act + (size_t)d * 256 + c4);
        float2 f0 = __half22float2(*(__half2*)&u.x);
        float2 f1 = __half22float2(*(__half2*)&u.y);
        val[0] = (s0 + f0.x) * dv;
        val[1] = (s1 + f0.y) * dv;
        val[2] = (s2 + f1.x) * dv;
        val[3] = (s3 + f1.y) * dv;
    }
    float hi[4], lo[4];
#pragma unroll
    for (int j = 0; j < 4; j++) {
        hi[j] = tf32r(val[j]);
        lo[j] = tf32r(val[j] - hi[j]);
    }
    if (dstTag == 0) {
        *(float4*)(g_ag0_hi + (size_t)d * 128 + c4) = make_float4(hi[0], hi[1], hi[2], hi[3]);
        *(float4*)(g_ag0_lo + (size_t)d * 128 + c4) = make_float4(lo[0], lo[1], lo[2], lo[3]);
    } else {
        *(float4*)(g_a_hi + (size_t)d * 256 + c4) = make_float4(hi[0], hi[1], hi[2], hi[3]);
        *(float4*)(g_a_lo + (size_t)d * 256 + c4) = make_float4(lo[0], lo[1], lo[2], lo[3]);
    }
}

// -------- cp.async double-buffered tf32 GEMM (3x split) ---------------------
// tile 128 x 64 x 16; 8 warps (4M x 2N). Epilogue: +bias, act,
// outMode 0: relu*dinv -> g_act fp16 (stride 256, pad zero); 1: sigmoid -> ext.
#define STG 7680
#define SMEM_TC (2 * STG * 4)

__global__ __launch_bounds__(256) void k_gemm_tc(
    int woff, int aTag, int lda, int Kpad, int C,
    const float* __restrict__ bias, float* __restrict__ extOut,
    int outMode, int ldo)
{
    extern __shared__ float sm[];
    const int tid = threadIdx.x;
    const int wid = tid >> 5, lid = tid & 31;
    const int warpM = wid & 3, warpN = wid >> 2;
    const int g = lid >> 2, tg = lid & 3;
    const int row0 = blockIdx.y * 128;
    const int col0 = blockIdx.x * 64;
    const uint32_t sb = (uint32_t)__cvta_generic_to_shared(sm);

    const float* baseHi = aTag ? g_a_hi : g_ag0_hi;
    const float* baseLo = aTag ? g_a_lo : g_ag0_lo;

    const float* aSrc[4]; uint32_t aDst[4];
    const float* bSrc[2]; uint32_t bDst[2];
#pragma unroll
    for (int i = 0; i < 4; i++) {
        int l = tid + i * 256;
        int r = (l & 511) >> 2, q = (l & 3) << 2;
        int gr = row0 + r; if (gr > NN - 1) gr = NN - 1;
        aSrc[i] = ((l < 512) ? baseHi : baseLo) + (size_t)gr * lda + q;
        aDst[i] = (uint32_t)(((l < 512) ? 0 : 2560) + r * 20 + q) * 4;
    }
#pragma unroll
    for (int i = 0; i < 2; i++) {
        int l = tid + i * 256;
        int r = (l & 255) >> 2, q = (l & 3) << 2;
        bSrc[i] = ((l < 256) ? g_wt_hi : g_wt_lo) + woff + (size_t)(col0 + r) * Kpad + q;
        bDst[i] = (uint32_t)(((l < 256) ? 5120 : 6400) + r * 20 + q) * 4;
    }

    float acc[2][4][4];
#pragma unroll
    for (int mt = 0; mt < 2; mt++)
#pragma unroll
        for (int nt = 0; nt < 4; nt++)
#pragma unroll
            for (int j = 0; j < 4; j++) acc[mt][nt][j] = 0.f;

    const int nch = Kpad >> 4;
#pragma unroll
    for (int i = 0; i < 4; i++) cpa16(sb + aDst[i], aSrc[i]);
#pragma unroll
    for (int i = 0; i < 2; i++) cpa16(sb + bDst[i], bSrc[i]);
    CP_COMMIT();

    for (int ch = 0; ch < nch; ch++) {
        if (ch + 1 < nch) {
            const uint32_t nOff = (uint32_t)((ch + 1) & 1) * (STG * 4);
            const int kt = (ch + 1) << 4;
#pragma unroll
            for (int i = 0; i < 4; i++) cpa16(sb + nOff + aDst[i], aSrc[i] + kt);
#pragma unroll
            for (int i = 0; i < 2; i++) cpa16(sb + nOff + bDst[i], bSrc[i] + kt);
        }
        CP_COMMIT();
        CP_WAIT1();
        __syncthreads();

        const float* As_hi = sm + (ch & 1) * STG;
        const float* As_lo = As_hi + 2560;
        const float* Bs_hi = As_hi + 5120;
        const float* Bs_lo = As_hi + 6400;

#pragma unroll
        for (int ks = 0; ks < 2; ks++) {
            const int kk = ks * 8;
            uint32_t ah[2][4], al[2][4], bh[4][2], bl[4][2];
#pragma unroll
            for (int mt = 0; mt < 2; mt++) {
                int rb = warpM * 32 + mt * 16;
                ah[mt][0] = __float_as_uint(As_hi[(rb + g)     * 20 + kk + tg]);
                ah[mt][1] = __float_as_uint(As_hi[(rb + g + 8) * 20 + kk + tg]);
                ah[mt][2] = __float_as_uint(As_hi[(rb + g)     * 20 + kk + tg + 4]);
                ah[mt][3] = __float_as_uint(As_hi[(rb + g + 8) * 20 + kk + tg + 4]);
                al[mt][0] = __float_as_uint(As_lo[(rb + g)     * 20 + kk + tg]);
                al[mt][1] = __float_as_uint(As_lo[(rb + g + 8) * 20 + kk + tg]);
                al[mt][2] = __float_as_uint(As_lo[(rb + g)     * 20 + kk + tg + 4]);
                al[mt][3] = __float_as_uint(As_lo[(rb + g + 8) * 20 + kk + tg + 4]);
            }
#pragma unroll
            for (int nt = 0; nt < 4; nt++) {
                int cb = warpN * 32 + nt * 8;
                bh[nt][0] = __float_as_uint(Bs_hi[(cb + g) * 20 + kk + tg]);
                bh[nt][1] = __float_as_uint(Bs_hi[(cb + g) * 20 + kk + tg + 4]);
                bl[nt][0] = __float_as_uint(Bs_lo[(cb + g) * 20 + kk + tg]);
                bl[nt][1] = __float_as_uint(Bs_lo[(cb + g) * 20 + kk + tg + 4]);
            }
#pragma unroll
            for (int mt = 0; mt < 2; mt++)
#pragma unroll
                for (int nt = 0; nt < 4; nt++) {
                    mma8(acc[mt][nt], ah[mt], bh[nt]);
                    mma8(acc[mt][nt], ah[mt], bl[nt]);
                    mma8(acc[mt][nt], al[mt], bh[nt]);
                }
        }
        __syncthreads();
    }

    // epilogue: +bias, activation, (dinv), store
#pragma unroll
    for (int mt = 0; mt < 2; mt++) {
#pragma unroll
        for (int half = 0; half < 2; half++) {
            int r = row0 + warpM * 32 + mt * 16 + g + half * 8;
            if (r >= NN) continue;
            float dv = g_dinv[r];
#pragma unroll
            for (int nt = 0; nt < 4; nt++) {
                int c = col0 + warpN * 32 + nt * 8 + tg * 2;
                float v0 = (c < C)     ? acc[mt][nt][half * 2 + 0] + bias[c]     : 0.f;
                float v1 = (c + 1 < C) ? acc[mt][nt][half * 2 + 1] + bias[c + 1] : 0.f;
                if (outMode == 0) {
                    v0 = (c < C)     ? fmaxf(v0, 0.f) * dv : 0.f;
                    v1 = (c + 1 < C) ? fmaxf(v1, 0.f) * dv : 0.f;
                    *(__half2*)(g_act + (size_t)r * 256 + c) = __floats2half2_rn(v0, v1);
                } else {
                    if (c < C)
                        extOut[(size_t)r * ldo + c] = 1.f / (1.f + expf(-v0));
                    if (c + 1 < C)
                        extOut[(size_t)r * ldo + c + 1] = 1.f / (1.f + expf(-v1));
                }
            }
        }
    }
}

// ---------------------------------------------------------------------------
// per-layer: AG = gather(A'); A'_next = act(AG @ W + b) [* dinv]
static void run_tower(const float* const* b, const int* Kd, const int* Cd,
                      const int* woff, float* finalOut, int ldoFinal)
{
    for (int l = 0; l < 4; l++) {
        int K = Kd[l], C = Cd[l];
        int Kpad = (K + 15) & ~15;
        int Npad64 = (C + 63) & ~63;

        if (l > 0) {
            int CpadW = (K + 15) & ~15;
            k_gather_split<<<NN, 64>>>(K, CpadW, 1);
        }
        int aTag = (l == 0) ? 0 : 1;
        int lda  = (l == 0) ? 128 : 256;
        dim3 gg(Npad64 / 64, NBLK);
        if (l < 3)
            k_gemm_tc<<<gg, 256, SMEM_TC>>>(woff[l], aTag, lda, Kpad, C,
                                            b[l], nullptr, 0, 0);
        else
            k_gemm_tc<<<gg, 256, SMEM_TC>>>(woff[l], aTag, lda, Kpad, C,
                                            b[l], finalOut, 1, ldoFinal);
    }
}

extern "C" void kernel_launch(void* const* d_in, const int* in_sizes, int n_in,
                              void* d_out, int out_size)
{
    const float* x = (const float*)d_in[0];
    const int* ei = (const int*)d_in[1];

    const float* We[4] = {(const float*)d_in[2], (const float*)d_in[4],
                          (const float*)d_in[6], (const float*)d_in[8]};
    const float* be[4] = {(const float*)d_in[3], (const float*)d_in[5],
                          (const float*)d_in[7], (const float*)d_in[9]};
    const float* Wn[4] = {(const float*)d_in[10], (const float*)d_in[12],
                          (const float*)d_in[14], (const float*)d_in[16]};
    const float* bn[4] = {(const float*)d_in[11], (const float*)d_in[13],
                          (const float*)d_in[15], (const float*)d_in[17]};

    float* out = (float*)d_out;

    cudaFuncSetAttribute(k_gemm_tc, cudaFuncAttributeMaxDynamicSharedMemorySize,
                         SMEM_TC);

    static const int Ke[4] = {128, 166, 192, 218};
    static const int Ce[4] = {166, 192, 218, 256};
    static const int Kn[4] = {128, 128, 128, 128};
    static const int Cn[4] = {128, 128, 128, 128};

    // combined W-prep descriptor (layers: e0..e3, v0..v3)
    WP8 p;
    int offE[4], offN[4];
    int off = 0, maxElems = 0;
    for (int l = 0; l < 8; l++) {
        int K = (l < 4) ? Ke[l] : Kn[l - 4];
        int C = (l < 4) ? Ce[l] : Cn[l - 4];
        p.W[l] = (l < 4) ? We[l] : Wn[l - 4];
        p.K[l] = K; p.C[l] = C;
        p.Kpad[l] = (K + 15) & ~15;
        p.Np[l]   = (C + 63) & ~63;
        p.off[l]  = off;
        if (l < 4) offE[l] = off; else offN[l - 4] = off;
        int elems = p.Kpad[l] * p.Np[l];
        if (elems > maxElems) maxElems = elems;
        off += elems;
    }
    // off == 230400 total; g_wt_hi/lo sized 231424

    // edge decode + graph normalization + CSR (shared by both towers)
    k_detect<<<1, 1>>>(ei);
    k_prep<<<(NE + 255) / 256, 256>>>(ei);
    k_zero_deg<<<(NN + 255) / 256, 256>>>();
    k_deg<<<(NE + 255) / 256, 256>>>();
    k_dinv<<<(NN + 255) / 256, 256>>>();
    k_scan<<<1, 1024>>>();
    k_place<<<(NE + 255) / 256, 256>>>();

    dim3 wg((maxElems + 255) / 256, 8);
    k_wprep8<<<wg, 256>>>(p);

    // shared first aggregation: A'_0 = x*dinv (fp16); AG0 = gather (128 ch)
    k_scale0<<<(NN * 32 + 255) / 256, 256>>>(x);
    k_gather_split<<<NN, 64>>>(128, 128, 0);

    // e tower -> out[0 : NN*256]
    run_tower(be, Ke, Ce, offE, out, 256);
    // v tower -> out[NN*256 : NN*256 + NN*128]
    run_tower(bn, Kn, Cn, offN, out + (size_t)NN * 256, 128);
}

// round 14
// speedup vs baseline: 1.1121x; 1.0596x over previous
#include <cuda_runtime.h>
#include <cuda_fp16.h>
#include <math.h>
#include <stdint.h>

#define NN 50000
#define NE 400000
#define NBLK 391                 // ceil(50000/128)

// ---------------- scratch (device globals; allocation-free) ----------------
// packed operand layout: per row, per k-group of 8, quad {hi(k+tg),hi(k+tg+4),
// lo(k+tg),lo(k+tg+4)} for tg=0..3 -> row length 2*Kpad floats.
__device__ __align__(16) float  g_apk[NN * 448];     // packed AG (max Kpad 224)
__device__ __align__(16) float  g_ag0[NN * 256];     // packed shared AG0 (Kpad 128)
__device__ __align__(16) __half g_act[NN * 256];     // A' = act*dinv (fp16), stride 256
__device__ __align__(16) float  g_wt[462848];        // packed W^T, all 8 layers
__device__ float g_dinv[NN];
__device__ int   g_deg[NN];
__device__ int2  g_edges[NE];
__device__ int   g_rowptr[NN + 1];
__device__ int   g_cursor[NN];
__device__ int   g_col[NE];
__device__ int   g_is64;

// ---------------- helpers ----------------
__device__ __forceinline__ float tf32r(float x) {
    uint32_t u;
    asm("cvt.rna.tf32.f32 %0, %1;" : "=r"(u) : "f"(x));
    return __uint_as_float(u);
}
__device__ __forceinline__ void mma8(float* c, const uint32_t* a, const uint32_t* b) {
    asm volatile(
        "mma.sync.aligned.m16n8k8.row.col.f32.tf32.tf32.f32 "
        "{%0,%1,%2,%3}, {%4,%5,%6,%7}, {%8,%9}, {%0,%1,%2,%3};"
        : "+f"(c[0]), "+f"(c[1]), "+f"(c[2]), "+f"(c[3])
        : "r"(a[0]), "r"(a[1]), "r"(a[2]), "r"(a[3]), "r"(b[0]), "r"(b[1]));
}
__device__ __forceinline__ void cpa16(uint32_t s, const void* g) {
    asm volatile("cp.async.ca.shared.global [%0], [%1], 16;" :: "r"(s), "l"(g));
}
#define CP_COMMIT() asm volatile("cp.async.commit_group;" ::: "memory")
#define CP_WAIT1()  asm volatile("cp.async.wait_group 1;" ::: "memory")

// ---------------- edge dtype sniff + decode ----------------
__global__ void k_detect(const int* __restrict__ e) {
    int all0 = 1;
    for (int i = 0; i < 128; i++)
        if (e[2 * i + 1] != 0) { all0 = 0; break; }
    g_is64 = all0;
}

__global__ void k_prep(const int* __restrict__ e) {
    int i = blockIdx.x * 256 + threadIdx.x;
    if (i >= NE) return;
    int s, d;
    if (g_is64) { s = e[2 * i]; d = e[2 * (NE + i)]; }
    else        { s = e[i];     d = e[NE + i]; }
    s = min(max(s, 0), NN - 1);
    d = min(max(d, 0), NN - 1);
    g_edges[i] = make_int2(s, d);
}

// ---------------- degree / dinv / CSR build ----------------
__global__ void k_zero_deg() {
    int i = blockIdx.x * 256 + threadIdx.x;
    if (i < NN) g_deg[i] = 0;
}
__global__ void k_deg() {
    int i = blockIdx.x * 256 + threadIdx.x;
    if (i < NE) atomicAdd(&g_deg[g_edges[i].y], 1);
}
__global__ void k_dinv() {
    int i = blockIdx.x * 256 + threadIdx.x;
    if (i < NN) g_dinv[i] = rsqrtf((float)(g_deg[i] + 1));
}

__global__ __launch_bounds__(1024) void k_scan() {
    __shared__ int ssum[1024];
    const int t = threadIdx.x;
    const int CH = (NN + 1023) / 1024;
    int beg = t * CH;
    int end = min(beg + CH, NN);
    int s = 0;
    for (int i = beg; i < end; i++) s += g_deg[i];
    ssum[t] = s;
    __syncthreads();
    for (int off = 1; off < 1024; off <<= 1) {
        int v = ssum[t];
        int u = (t >= off) ? ssum[t - off] : 0;
        __syncthreads();
        ssum[t] = v + u;
        __syncthreads();
    }
    int run = (t == 0) ? 0 : ssum[t - 1];
    for (int i = beg; i < end; i++) {
        g_rowptr[i] = run;
        g_cursor[i] = run;
        run += g_deg[i];
    }
    if (t == 1023) g_rowptr[NN] = run;
}

__global__ void k_place() {
    int i = blockIdx.x * 256 + threadIdx.x;
    if (i >= NE) return;
    int2 sd = g_edges[i];
    int pos = atomicAdd(&g_cursor[sd.y], 1);
    g_col[pos] = sd.x;
}

// -------- A'_0 = x * dinv (fp16, stride 256) --------------------------------
__global__ void k_scale0(const float* __restrict__ x) {
    int i = blockIdx.x * 256 + threadIdx.x;      // quad index
    if (i >= NN * 32) return;
    int n = i >> 5, q = (i & 31) << 2;
    float dv = g_dinv[n];
    float4 v = *(const float4*)(x + (size_t)n * 128 + q);
    __half2 h0 = __floats2half2_rn(v.x * dv, v.y * dv);
    __half2 h1 = __floats2half2_rn(v.z * dv, v.w * dv);
    uint2 u;
    u.x = *(uint32_t*)&h0;
    u.y = *(uint32_t*)&h1;
    *(uint2*)(g_act + (size_t)n * 256 + q) = u;
}

// -------- all-layer W prep: transpose + tf32 split, packed ------------------
struct WP8 {
    const float* W[8];
    int K[8], C[8], Kpad[8], Np[8], off[8];   // off = packed float offset
};
__global__ void k_wprep8(WP8 p) {
    int l = blockIdx.y;
    int i = blockIdx.x * 256 + threadIdx.x;
    if (i >= p.Np[l] * p.Kpad[l]) return;
    int n = i / p.Kpad[l], k = i % p.Kpad[l];
    float w = (n < p.C[l] && k < p.K[l]) ? p.W[l][(size_t)k * p.C[l] + n] : 0.f;
    float hi = tf32r(w);
    int pos = p.off[l] + n * 2 * p.Kpad[l] + (k >> 3) * 16 + (k & 3) * 4 + ((k >> 2) & 1);
    g_wt[pos]     = hi;
    g_wt[pos + 2] = tf32r(w - hi);
}

// -------- gather: AG[d] = dinv_d*(sum A'[s] + A'[d]); packed split output ---
// block 64 thr, 1 node; thread = 4 consecutive channels. dstTag 0 -> g_ag0
// (rowlen 256), 1 -> g_apk (rowlen = 2*KpadW). Zero-fills [C, CpadW).
__global__ __launch_bounds__(64) void k_gather_split(int C, int CpadW, int dstTag,
                                                     int rowlen)
{
    __shared__ int scol[64];
    const int d = blockIdx.x;
    const int beg = g_rowptr[d];
    const int deg = g_rowptr[d + 1] - beg;
    const int c4 = threadIdx.x << 2;

    float s0 = 0.f, s1 = 0.f, s2 = 0.f, s3 = 0.f;
    for (int done = 0; done < deg; done += 64) {
        int chunk = min(deg - done, 64);
        if (threadIdx.x < chunk) scol[threadIdx.x] = g_col[beg + done + threadIdx.x];
        __syncthreads();
        if (c4 < C) {
            for (int i = 0; i < chunk; i++) {
                uint2 u = *(const uint2*)(g_act + (size_t)scol[i] * 256 + c4);
                float2 f0 = __half22float2(*(__half2*)&u.x);
                float2 f1 = __half22float2(*(__half2*)&u.y);
                s0 += f0.x; s1 += f0.y; s2 += f1.x; s3 += f1.y;
            }
        }
        __syncthreads();
    }
    if (c4 >= CpadW) return;

    float val[4] = {0.f, 0.f, 0.f, 0.f};
    if (c4 < C) {
        const float dv = g_dinv[d];
        uint2 u = *(const uint2*)(g_act + (size_t)d * 256 + c4);
        float2 f0 = __half22float2(*(__half2*)&u.x);
        float2 f1 = __half22float2(*(__half2*)&u.y);
        val[0] = (s0 + f0.x) * dv;
        val[1] = (s1 + f0.y) * dv;
        val[2] = (s2 + f1.x) * dv;
        val[3] = (s3 + f1.y) * dv;
    }
    float* dst = dstTag ? g_apk : g_ag0;
    // packed position: channel c -> quad (c>>3)*16 + tg*4 + half, tg=c&3
    int base = d * rowlen + ((c4 >> 3) << 4) + ((c4 >> 2) & 1);
#pragma unroll
    for (int j = 0; j < 4; j++) {
        float hi = tf32r(val[j]);
        dst[base + j * 4]     = hi;
        dst[base + j * 4 + 2] = tf32r(val[j] - hi);
    }
}

// -------- cp.async double-buffered tf32 GEMM (3x split), packed frags -------
// tile 128 x 64 x 16; 8 warps (4M x 2N).
// smem stage: A 128 rows x 48 fl (data 32) @0; B 64 x 48 @6144; stage 9216 fl.
#define STG_F 9216
#define SMEM_TC (2 * STG_F * 4)

__global__ __launch_bounds__(256) void k_gemm_tc(
    int woff, int aTag, int ldaP, int Kpad, int C,
    const float* __restrict__ bias, float* __restrict__ extOut,
    int outMode, int ldo)
{
    extern __shared__ float sm[];
    const int tid = threadIdx.x;
    const int wid = tid >> 5, lid = tid & 31;
    const int warpM = wid & 3, warpN = wid >> 2;
    const int g = lid >> 2, tg = lid & 3;
    const int row0 = blockIdx.y * 128;
    const int col0 = blockIdx.x * 64;
    const uint32_t sb = (uint32_t)__cvta_generic_to_shared(sm);
    const int ldbP = 2 * Kpad;

    const float* Abase = aTag ? g_apk : g_ag0;

    // staging coords: quad j of row: off = (j>>2)*16 + (j&3)*4 floats
    const float* aSrc[4]; uint32_t aDst[4];
    const float* bSrc[2]; uint32_t bDst[2];
#pragma unroll
    for (int i = 0; i < 4; i++) {
        int l = tid + i * 256;          // 0..1023
        int r = l >> 3, j = l & 7;
        int gr = row0 + r; if (gr > NN - 1) gr = NN - 1;
        int qo = ((j >> 2) << 4) + ((j & 3) << 2);
        aSrc[i] = Abase + (size_t)gr * ldaP + qo;
        aDst[i] = (uint32_t)(r * 48 + qo) * 4;
    }
#pragma unroll
    for (int i = 0; i < 2; i++) {
        int l = tid + i * 256;          // 0..511
        int r = l >> 3, j = l & 7;
        int qo = ((j >> 2) << 4) + ((j & 3) << 2);
        bSrc[i] = g_wt + woff + (size_t)(col0 + r) * ldbP + qo;
        bDst[i] = (uint32_t)(6144 + r * 48 + qo) * 4;
    }

    float acc[2][4][4];
#pragma unroll
    for (int mt = 0; mt < 2; mt++)
#pragma unroll
        for (int nt = 0; nt < 4; nt++)
#pragma unroll
            for (int j = 0; j < 4; j++) acc[mt][nt][j] = 0.f;

    const int nch = Kpad >> 4;          // 32 packed floats per chunk per row
#pragma unroll
    for (int i = 0; i < 4; i++) cpa16(sb + aDst[i], aSrc[i]);
#pragma unroll
    for (int i = 0; i < 2; i++) cpa16(sb + bDst[i], bSrc[i]);
    CP_COMMIT();

    for (int ch = 0; ch < nch; ch++) {
        if (ch + 1 < nch) {
            const uint32_t nOff = (uint32_t)((ch + 1) & 1) * (STG_F * 4);
            const int kt = (ch + 1) * 32;
#pragma unroll
            for (int i = 0; i < 4; i++) cpa16(sb + nOff + aDst[i], aSrc[i] + kt);
#pragma unroll
            for (int i = 0; i < 2; i++) cpa16(sb + nOff + bDst[i], bSrc[i] + kt);
        }
        CP_COMMIT();
        CP_WAIT1();
        __syncthreads();

        const float* st = sm + (ch & 1) * STG_F;

#pragma unroll
        for (int ks = 0; ks < 2; ks++) {
            const int colo = ks * 16 + tg * 4;
            uint32_t ah[2][4], al[2][4], bh[4][2], bl[4][2];
#pragma unroll
            for (int mt = 0; mt < 2; mt++) {
                int rA = warpM * 32 + mt * 16 + g;
                float4 qg  = *(const float4*)(st + rA * 48 + colo);
                float4 qg8 = *(const float4*)(st + (rA + 8) * 48 + colo);
                ah[mt][0] = __float_as_uint(qg.x);
                ah[mt][1] = __float_as_uint(qg8.x);
                ah[mt][2] = __float_as_uint(qg.y);
                ah[mt][3] = __float_as_uint(qg8.y);
                al[mt][0] = __float_as_uint(qg.z);
                al[mt][1] = __float_as_uint(qg8.z);
                al[mt][2] = __float_as_uint(qg.w);
                al[mt][3] = __float_as_uint(qg8.w);
            }
#pragma unroll
            for (int nt = 0; nt < 4; nt++) {
                int rB = warpN * 32 + nt * 8 + g;
                float4 qb = *(const float4*)(st + 6144 + rB * 48 + colo);
                bh[nt][0] = __float_as_uint(qb.x);
                bh[nt][1] = __float_as_uint(qb.y);
                bl[nt][0] = __float_as_uint(qb.z);
                bl[nt][1] = __float_as_uint(qb.w);
            }
#pragma unroll
            for (int mt = 0; mt < 2; mt++)
#pragma unroll
                for (int nt = 0; nt < 4; nt++) {
                    mma8(acc[mt][nt], ah[mt], bh[nt]);
                    mma8(acc[mt][nt], ah[mt], bl[nt]);
                    mma8(acc[mt][nt], al[mt], bh[nt]);
                }
        }
        __syncthreads();
    }

    // epilogue: +bias, activation, (dinv), store
#pragma unroll
    for (int mt = 0; mt < 2; mt++) {
#pragma unroll
        for (int half = 0; half < 2; half++) {
            int r = row0 + warpM * 32 + mt * 16 + g + half * 8;
            if (r >= NN) continue;
            float dv = g_dinv[r];
#pragma unroll
            for (int nt = 0; nt < 4; nt++) {
                int c = col0 + warpN * 32 + nt * 8 + tg * 2;
                float v0 = (c < C)     ? acc[mt][nt][half * 2 + 0] + bias[c]     : 0.f;
                float v1 = (c + 1 < C) ? acc[mt][nt][half * 2 + 1] + bias[c + 1] : 0.f;
                if (outMode == 0) {
                    v0 = (c < C)     ? fmaxf(v0, 0.f) * dv : 0.f;
                    v1 = (c + 1 < C) ? fmaxf(v1, 0.f) * dv : 0.f;
                    *(__half2*)(g_act + (size_t)r * 256 + c) = __floats2half2_rn(v0, v1);
                } else {
                    if (c < C)
                        extOut[(size_t)r * ldo + c] = 1.f / (1.f + expf(-v0));
                    if (c + 1 < C)
                        extOut[(size_t)r * ldo + c + 1] = 1.f / (1.f + expf(-v1));
                }
            }
        }
    }
}

// ---------------------------------------------------------------------------
// per-layer: AG = gather(A'); A'_next = act(AG @ W + b) [* dinv]
static void run_tower(const float* const* b, const int* Kd, const int* Cd,
                      const int* woff, float* finalOut, int ldoFinal)
{
    for (int l = 0; l < 4; l++) {
        int K = Kd[l], C = Cd[l];
        int Kpad = (K + 15) & ~15;
        int Npad64 = (C + 63) & ~63;

        if (l > 0)
            k_gather_split<<<NN, 64>>>(K, Kpad, 1, 2 * Kpad);
        int aTag = (l == 0) ? 0 : 1;
        int ldaP = (l == 0) ? 256 : 2 * Kpad;
        dim3 gg(Npad64 / 64, NBLK);
        if (l < 3)
            k_gemm_tc<<<gg, 256, SMEM_TC>>>(woff[l], aTag, ldaP, Kpad, C,
                                            b[l], nullptr, 0, 0);
        else
            k_gemm_tc<<<gg, 256, SMEM_TC>>>(woff[l], aTag, ldaP, Kpad, C,
                                            b[l], finalOut, 1, ldoFinal);
    }
}

extern "C" void kernel_launch(void* const* d_in, const int* in_sizes, int n_in,
                              void* d_out, int out_size)
{
    const float* x = (const float*)d_in[0];
    const int* ei = (const int*)d_in[1];

    const float* We[4] = {(const float*)d_in[2], (const float*)d_in[4],
                          (const float*)d_in[6], (const float*)d_in[8]};
    const float* be[4] = {(const float*)d_in[3], (const float*)d_in[5],
                          (const float*)d_in[7], (const float*)d_in[9]};
    const float* Wn[4] = {(const float*)d_in[10], (const float*)d_in[12],
                          (const float*)d_in[14], (const float*)d_in[16]};
    const float* bn[4] = {(const float*)d_in[11], (const float*)d_in[13],
                          (const float*)d_in[15], (const float*)d_in[17]};

    float* out = (float*)d_out;

    cudaFuncSetAttribute(k_gemm_tc, cudaFuncAttributeMaxDynamicSharedMemorySize,
                         SMEM_TC);

    static const int Ke[4] = {128, 166, 192, 218};
    static const int Ce[4] = {166, 192, 218, 256};
    static const int Kn[4] = {128, 128, 128, 128};
    static const int Cn[4] = {128, 128, 128, 128};

    // combined W-prep descriptor (layers: e0..e3, v0..v3); packed offsets
    WP8 p;
    int offE[4], offN[4];
    int off = 0, maxElems = 0;
    for (int l = 0; l < 8; l++) {
        int K = (l < 4) ? Ke[l] : Kn[l - 4];
        int C = (l < 4) ? Ce[l] : Cn[l - 4];
        p.W[l] = (l < 4) ? We[l] : Wn[l - 4];
        p.K[l] = K; p.C[l] = C;
        p.Kpad[l] = (K + 15) & ~15;
        p.Np[l]   = (C + 63) & ~63;
        p.off[l]  = off;
        if (l < 4) offE[l] = off; else offN[l - 4] = off;
        int elems = p.Kpad[l] * p.Np[l];
        if (elems > maxElems) maxElems = elems;
        off += 2 * elems;                     // hi+lo packed together
    }
    // off == 460800 packed floats; g_wt sized 462848

    // edge decode + graph normalization + CSR (shared by both towers)
    k_detect<<<1, 1>>>(ei);
    k_prep<<<(NE + 255) / 256, 256>>>(ei);
    k_zero_deg<<<(NN + 255) / 256, 256>>>();
    k_deg<<<(NE + 255) / 256, 256>>>();
    k_dinv<<<(NN + 255) / 256, 256>>>();
    k_scan<<<1, 1024>>>();
    k_place<<<(NE + 255) / 256, 256>>>();

    dim3 wg((maxElems + 255) / 256, 8);
    k_wprep8<<<wg, 256>>>(p);

    // shared first aggregation: A'_0 = x*dinv (fp16); AG0 packed (Kpad 128)
    k_scale0<<<(NN * 32 + 255) / 256, 256>>>(x);
    k_gather_split<<<NN, 64>>>(128, 128, 0, 256);

    // e tower -> out[0 : NN*256]
    run_tower(be, Ke, Ce, offE, out, 256);
    // v tower -> out[NN*256 : NN*256 + NN*128]
    run_tower(bn, Kn, Cn, offN, out + (size_t)NN * 256, 128);
}

// round 15
// speedup vs baseline: 1.5586x; 1.4016x over previous
#include <cuda_runtime.h>
#include <cuda_fp16.h>
#include <cuda_bf16.h>
#include <math.h>
#include <stdint.h>

#define NN 50000
#define NE 400000
#define NBLK 391                 // ceil(50000/128)

// ---------------- scratch (device globals; allocation-free) ----------------
// packed bf16 operand layout: per row, per k-group of 16, quad (16B = 8 bf16):
// {hi(2tg),hi(2tg+1), hi(2tg+8),hi(2tg+9), lo(2tg),lo(2tg+1), lo(2tg+8),lo(2tg+9)}
// row length = 2*Kpad bf16.
__device__ __align__(16) __nv_bfloat16 g_apk[NN * 448];  // packed AG (max Kpad 224)
__device__ __align__(16) __nv_bfloat16 g_ag0[NN * 256];  // packed shared AG0 (K=128)
__device__ __align__(16) __half        g_act[NN * 256];  // A' = act*dinv (fp16)
__device__ __align__(16) __nv_bfloat16 g_wt[468992];     // packed W^T, all 8 layers
__device__ float g_dinv[NN];
__device__ int   g_deg[NN];
__device__ int2  g_edges[NE];
__device__ int   g_rowptr[NN + 1];
__device__ int   g_cursor[NN];
__device__ int   g_col[NE];
__device__ int   g_is64;

// ---------------- helpers ----------------
__device__ __forceinline__ void mma16(float* c, const uint32_t* a, const uint32_t* b) {
    asm volatile(
        "mma.sync.aligned.m16n8k16.row.col.f32.bf16.bf16.f32 "
        "{%0,%1,%2,%3}, {%4,%5,%6,%7}, {%8,%9}, {%0,%1,%2,%3};"
        : "+f"(c[0]), "+f"(c[1]), "+f"(c[2]), "+f"(c[3])
        : "r"(a[0]), "r"(a[1]), "r"(a[2]), "r"(a[3]), "r"(b[0]), "r"(b[1]));
}
__device__ __forceinline__ void cpa16(uint32_t s, const void* g) {
    asm volatile("cp.async.ca.shared.global [%0], [%1], 16;" :: "r"(s), "l"(g));
}
#define CP_COMMIT() asm volatile("cp.async.commit_group;" ::: "memory")
#define CP_WAIT1()  asm volatile("cp.async.wait_group 1;" ::: "memory")

// ---------------- edge dtype sniff + decode ----------------
__global__ void k_detect(const int* __restrict__ e) {
    int all0 = 1;
    for (int i = 0; i < 128; i++)
        if (e[2 * i + 1] != 0) { all0 = 0; break; }
    g_is64 = all0;
}

__global__ void k_prep(const int* __restrict__ e) {
    int i = blockIdx.x * 256 + threadIdx.x;
    if (i >= NE) return;
    int s, d;
    if (g_is64) { s = e[2 * i]; d = e[2 * (NE + i)]; }
    else        { s = e[i];     d = e[NE + i]; }
    s = min(max(s, 0), NN - 1);
    d = min(max(d, 0), NN - 1);
    g_edges[i] = make_int2(s, d);
}

// ---------------- degree / dinv / CSR build ----------------
__global__ void k_zero_deg() {
    int i = blockIdx.x * 256 + threadIdx.x;
    if (i < NN) g_deg[i] = 0;
}
__global__ void k_deg() {
    int i = blockIdx.x * 256 + threadIdx.x;
    if (i < NE) atomicAdd(&g_deg[g_edges[i].y], 1);
}
__global__ void k_dinv() {
    int i = blockIdx.x * 256 + threadIdx.x;
    if (i < NN) g_dinv[i] = rsqrtf((float)(g_deg[i] + 1));
}

__global__ __launch_bounds__(1024) void k_scan() {
    __shared__ int ssum[1024];
    const int t = threadIdx.x;
    const int CH = (NN + 1023) / 1024;
    int beg = t * CH;
    int end = min(beg + CH, NN);
    int s = 0;
    for (int i = beg; i < end; i++) s += g_deg[i];
    ssum[t] = s;
    __syncthreads();
    for (int off = 1; off < 1024; off <<= 1) {
        int v = ssum[t];
        int u = (t >= off) ? ssum[t - off] : 0;
        __syncthreads();
        ssum[t] = v + u;
        __syncthreads();
    }
    int run = (t == 0) ? 0 : ssum[t - 1];
    for (int i = beg; i < end; i++) {
        g_rowptr[i] = run;
        g_cursor[i] = run;
        run += g_deg[i];
    }
    if (t == 1023) g_rowptr[NN] = run;
}

__global__ void k_place() {
    int i = blockIdx.x * 256 + threadIdx.x;
    if (i >= NE) return;
    int2 sd = g_edges[i];
    int pos = atomicAdd(&g_cursor[sd.y], 1);
    g_col[pos] = sd.x;
}

// -------- A'_0 = x * dinv (fp16, stride 256) --------------------------------
__global__ void k_scale0(const float* __restrict__ x) {
    int i = blockIdx.x * 256 + threadIdx.x;      // quad index
    if (i >= NN * 32) return;
    int n = i >> 5, q = (i & 31) << 2;
    float dv = g_dinv[n];
    float4 v = *(const float4*)(x + (size_t)n * 128 + q);
    __half2 h0 = __floats2half2_rn(v.x * dv, v.y * dv);
    __half2 h1 = __floats2half2_rn(v.z * dv, v.w * dv);
    uint2 u;
    u.x = *(uint32_t*)&h0;
    u.y = *(uint32_t*)&h1;
    *(uint2*)(g_act + (size_t)n * 256 + q) = u;
}

// -------- all-layer W prep: transpose + bf16 hi/lo split, packed ------------
struct WP8 {
    const float* W[8];
    int K[8], C[8], Kpad[8], Np[8], off[8];   // off = packed bf16 offset
};
__global__ void k_wprep8(WP8 p) {
    int l = blockIdx.y;
    int i = blockIdx.x * 256 + threadIdx.x;
    if (i >= p.Np[l] * p.Kpad[l]) return;
    int n = i / p.Kpad[l], k = i % p.Kpad[l];
    float w = (n < p.C[l] && k < p.K[l]) ? p.W[l][(size_t)k * p.C[l] + n] : 0.f;
    __nv_bfloat16 hi = __float2bfloat16_rn(w);
    __nv_bfloat16 lo = __float2bfloat16_rn(w - __bfloat162float(hi));
    int kg = k >> 4, pp = k & 15, pair = pp >> 1, elem = pp & 1;
    int tg = pair & 3, sec = pair >> 2;
    int base = p.off[l] + n * 2 * p.Kpad[l] + kg * 32 + tg * 8 + sec * 2 + elem;
    g_wt[base]     = hi;
    g_wt[base + 4] = lo;
}

// -------- gather: AG[d] = dinv_d*(sum A'[s] + A'[d]); packed bf16 split -----
// block 64 thr, 1 node; thread = 4 consecutive channels. dstTag 0 -> g_ag0,
// 1 -> g_apk. rowlen in bf16 elems (= 2*Kpad). Zero-fills [C, CpadW).
__global__ __launch_bounds__(64) void k_gather_split(int C, int CpadW, int dstTag,
                                                     int rowlen)
{
    __shared__ int scol[64];
    const int d = blockIdx.x;
    const int beg = g_rowptr[d];
    const int deg = g_rowptr[d + 1] - beg;
    const int c4 = threadIdx.x << 2;

    float s0 = 0.f, s1 = 0.f, s2 = 0.f, s3 = 0.f;
    for (int done = 0; done < deg; done += 64) {
        int chunk = min(deg - done, 64);
        if (threadIdx.x < chunk) scol[threadIdx.x] = g_col[beg + done + threadIdx.x];
        __syncthreads();
        if (c4 < C) {
            for (int i = 0; i < chunk; i++) {
                uint2 u = *(const uint2*)(g_act + (size_t)scol[i] * 256 + c4);
                float2 f0 = __half22float2(*(__half2*)&u.x);
                float2 f1 = __half22float2(*(__half2*)&u.y);
                s0 += f0.x; s1 += f0.y; s2 += f1.x; s3 += f1.y;
            }
        }
        __syncthreads();
    }
    if (c4 >= CpadW) return;

    float val[4] = {0.f, 0.f, 0.f, 0.f};
    if (c4 < C) {
        const float dv = g_dinv[d];
        uint2 u = *(const uint2*)(g_act + (size_t)d * 256 + c4);
        float2 f0 = __half22float2(*(__half2*)&u.x);
        float2 f1 = __half22float2(*(__half2*)&u.y);
        val[0] = (s0 + f0.x) * dv;
        val[1] = (s1 + f0.y) * dv;
        val[2] = (s2 + f1.x) * dv;
        val[3] = (s3 + f1.y) * dv;
    }
    __nv_bfloat16* dst = dstTag ? g_apk : g_ag0;
    const int kg = c4 >> 4;
    const int pair0 = (c4 & 15) >> 1;
#pragma unroll
    for (int j2 = 0; j2 < 2; j2++) {
        int pair = pair0 + j2;
        int tg = pair & 3, sec = pair >> 2;
        int hp = d * rowlen + kg * 32 + tg * 8 + sec * 2;
        float v0 = val[2 * j2], v1 = val[2 * j2 + 1];
        __nv_bfloat16 h0 = __float2bfloat16_rn(v0);
        __nv_bfloat16 h1 = __float2bfloat16_rn(v1);
        __nv_bfloat16 l0 = __float2bfloat16_rn(v0 - __bfloat162float(h0));
        __nv_bfloat16 l1 = __float2bfloat16_rn(v1 - __bfloat162float(h1));
        __nv_bfloat162 hh; hh.x = h0; hh.y = h1;
        __nv_bfloat162 ll; ll.x = l0; ll.y = l1;
        *(__nv_bfloat162*)(dst + hp)     = hh;
        *(__nv_bfloat162*)(dst + hp + 4) = ll;
    }
}

// -------- cp.async double-buffered bf16x3 GEMM, packed fragments ------------
// tile 128 x 64 x 32; 8 warps (4M x 2N). smem stage: A 128 rows x 192B @0,
// B 64 rows x 192B @24576; stage 36864B.
#define STG_B 36864
#define SMEM_TC (2 * STG_B)

__global__ __launch_bounds__(256) void k_gemm_tc(
    int woff, int aTag, int ldaH, int Kpad, int C,
    const float* __restrict__ bias, float* __restrict__ extOut,
    int outMode, int ldo)
{
    extern __shared__ char smc[];
    const int tid = threadIdx.x;
    const int wid = tid >> 5, lid = tid & 31;
    const int warpM = wid & 3, warpN = wid >> 2;
    const int g = lid >> 2, tg = lid & 3;
    const int row0 = blockIdx.y * 128;
    const int col0 = blockIdx.x * 64;
    const uint32_t sb = (uint32_t)__cvta_generic_to_shared(smc);
    const int ldbH = 2 * Kpad;

    const __nv_bfloat16* Abase = aTag ? g_apk : g_ag0;

    const __nv_bfloat16* aSrc[4]; uint32_t aDst[4];
    const __nv_bfloat16* bSrc[2]; uint32_t bDst[2];
#pragma unroll
    for (int i = 0; i < 4; i++) {
        int l = tid + i * 256;          // 0..1023 : (row, quad j of 8)
        int r = l >> 3, j = l & 7;
        int gr = row0 + r; if (gr > NN - 1) gr = NN - 1;
        aSrc[i] = Abase + (size_t)gr * ldaH + j * 8;
        aDst[i] = (uint32_t)(r * 192 + j * 16);
    }
#pragma unroll
    for (int i = 0; i < 2; i++) {
        int l = tid + i * 256;          // 0..511
        int r = l >> 3, j = l & 7;
        bSrc[i] = g_wt + woff + (size_t)(col0 + r) * ldbH + j * 8;
        bDst[i] = (uint32_t)(24576 + r * 192 + j * 16);
    }

    float acc[2][4][4];
#pragma unroll
    for (int mt = 0; mt < 2; mt++)
#pragma unroll
        for (int nt = 0; nt < 4; nt++)
#pragma unroll
            for (int j = 0; j < 4; j++) acc[mt][nt][j] = 0.f;

    const int nch = Kpad >> 5;          // 64 bf16 (=2 k16 groups) per chunk/row
#pragma unroll
    for (int i = 0; i < 4; i++) cpa16(sb + aDst[i], aSrc[i]);
#pragma unroll
    for (int i = 0; i < 2; i++) cpa16(sb + bDst[i], bSrc[i]);
    CP_COMMIT();

    for (int ch = 0; ch < nch; ch++) {
        if (ch + 1 < nch) {
            const uint32_t nOff = (uint32_t)((ch + 1) & 1) * STG_B;
            const int kt = (ch + 1) * 64;
#pragma unroll
            for (int i = 0; i < 4; i++) cpa16(sb + nOff + aDst[i], aSrc[i] + kt);
#pragma unroll
            for (int i = 0; i < 2; i++) cpa16(sb + nOff + bDst[i], bSrc[i] + kt);
        }
        CP_COMMIT();
        CP_WAIT1();
        __syncthreads();

        const char* st = smc + (ch & 1) * STG_B;

#pragma unroll
        for (int ks = 0; ks < 2; ks++) {
            const int colo = ks * 64 + tg * 16;
            uint32_t ah[2][4], al[2][4], bh[4][2], bl[4][2];
#pragma unroll
            for (int mt = 0; mt < 2; mt++) {
                int rA = warpM * 32 + mt * 16 + g;
                uint4 qg  = *(const uint4*)(st + rA * 192 + colo);
                uint4 qg8 = *(const uint4*)(st + (rA + 8) * 192 + colo);
                ah[mt][0] = qg.x;  ah[mt][1] = qg8.x;
                ah[mt][2] = qg.y;  ah[mt][3] = qg8.y;
                al[mt][0] = qg.z;  al[mt][1] = qg8.z;
                al[mt][2] = qg.w;  al[mt][3] = qg8.w;
            }
#pragma unroll
            for (int nt = 0; nt < 4; nt++) {
                int rB = warpN * 32 + nt * 8 + g;
                uint4 qb = *(const uint4*)(st + 24576 + rB * 192 + colo);
                bh[nt][0] = qb.x;  bh[nt][1] = qb.y;
                bl[nt][0] = qb.z;  bl[nt][1] = qb.w;
            }
#pragma unroll
            for (int mt = 0; mt < 2; mt++)
#pragma unroll
                for (int nt = 0; nt < 4; nt++) {
                    mma16(acc[mt][nt], ah[mt], bh[nt]);
                    mma16(acc[mt][nt], ah[mt], bl[nt]);
                    mma16(acc[mt][nt], al[mt], bh[nt]);
                }
        }
        __syncthreads();
    }

    // epilogue: +bias, activation, (dinv), store
#pragma unroll
    for (int mt = 0; mt < 2; mt++) {
#pragma unroll
        for (int half = 0; half < 2; half++) {
            int r = row0 + warpM * 32 + mt * 16 + g + half * 8;
            if (r >= NN) continue;
            float dv = g_dinv[r];
#pragma unroll
            for (int nt = 0; nt < 4; nt++) {
                int c = col0 + warpN * 32 + nt * 8 + tg * 2;
                float v0 = (c < C)     ? acc[mt][nt][half * 2 + 0] + bias[c]     : 0.f;
                float v1 = (c + 1 < C) ? acc[mt][nt][half * 2 + 1] + bias[c + 1] : 0.f;
                if (outMode == 0) {
                    v0 = (c < C)     ? fmaxf(v0, 0.f) * dv : 0.f;
                    v1 = (c + 1 < C) ? fmaxf(v1, 0.f) * dv : 0.f;
                    *(__half2*)(g_act + (size_t)r * 256 + c) = __floats2half2_rn(v0, v1);
                } else {
                    if (c < C)
                        extOut[(size_t)r * ldo + c] = 1.f / (1.f + expf(-v0));
                    if (c + 1 < C)
                        extOut[(size_t)r * ldo + c + 1] = 1.f / (1.f + expf(-v1));
                }
            }
        }
    }
}

// ---------------------------------------------------------------------------
// per-layer: AG = gather(A'); A'_next = act(AG @ W + b) [* dinv]
static void run_tower(const float* const* b, const int* Kd, const int* Cd,
                      const int* woff, float* finalOut, int ldoFinal)
{
    for (int l = 0; l < 4; l++) {
        int K = Kd[l], C = Cd[l];
        int Kpad = (K + 31) & ~31;
        int Npad64 = (C + 63) & ~63;

        if (l > 0)
            k_gather_split<<<NN, 64>>>(K, Kpad, 1, 2 * Kpad);
        int aTag = (l == 0) ? 0 : 1;
        int ldaH = (l == 0) ? 256 : 2 * Kpad;
        dim3 gg(Npad64 / 64, NBLK);
        if (l < 3)
            k_gemm_tc<<<gg, 256, SMEM_TC>>>(woff[l], aTag, ldaH, Kpad, C,
                                            b[l], nullptr, 0, 0);
        else
            k_gemm_tc<<<gg, 256, SMEM_TC>>>(woff[l], aTag, ldaH, Kpad, C,
                                            b[l], finalOut, 1, ldoFinal);
    }
}

extern "C" void kernel_launch(void* const* d_in, const int* in_sizes, int n_in,
                              void* d_out, int out_size)
{
    const float* x = (const float*)d_in[0];
    const int* ei = (const int*)d_in[1];

    const float* We[4] = {(const float*)d_in[2], (const float*)d_in[4],
                          (const float*)d_in[6], (const float*)d_in[8]};
    const float* be[4] = {(const float*)d_in[3], (const float*)d_in[5],
                          (const float*)d_in[7], (const float*)d_in[9]};
    const float* Wn[4] = {(const float*)d_in[10], (const float*)d_in[12],
                          (const float*)d_in[14], (const float*)d_in[16]};
    const float* bn[4] = {(const float*)d_in[11], (const float*)d_in[13],
                          (const float*)d_in[15], (const float*)d_in[17]};

    float* out = (float*)d_out;

    cudaFuncSetAttribute(k_gemm_tc, cudaFuncAttributeMaxDynamicSharedMemorySize,
                         SMEM_TC);

    static const int Ke[4] = {128, 166, 192, 218};
    static const int Ce[4] = {166, 192, 218, 256};
    static const int Kn[4] = {128, 128, 128, 128};
    static const int Cn[4] = {128, 128, 128, 128};

    // combined W-prep descriptor (layers: e0..e3, v0..v3); packed bf16 offsets
    WP8 p;
    int offE[4], offN[4];
    int off = 0, maxElems = 0;
    for (int l = 0; l < 8; l++) {
        int K = (l < 4) ? Ke[l] : Kn[l - 4];
        int C = (l < 4) ? Ce[l] : Cn[l - 4];
        p.W[l] = (l < 4) ? We[l] : Wn[l - 4];
        p.K[l] = K; p.C[l] = C;
        p.Kpad[l] = (K + 31) & ~31;
        p.Np[l]   = (C + 63) & ~63;
        p.off[l]  = off;
        if (l < 4) offE[l] = off; else offN[l - 4] = off;
        int elems = p.Kpad[l] * p.Np[l];
        if (elems > maxElems) maxElems = elems;
        off += 2 * elems;                     // hi+lo packed together
    }
    // off = 2*(128*192+192*192+192*256+224*256 + 4*128*128) = 466944 <= 468992

    // edge decode + graph normalization + CSR (shared by both towers)
    k_detect<<<1, 1>>>(ei);
    k_prep<<<(NE + 255) / 256, 256>>>(ei);
    k_zero_deg<<<(NN + 255) / 256, 256>>>();
    k_deg<<<(NE + 255) / 256, 256>>>();
    k_dinv<<<(NN + 255) / 256, 256>>>();
    k_scan<<<1, 1024>>>();
    k_place<<<(NE + 255) / 256, 256>>>();

    dim3 wg((maxElems + 255) / 256, 8);
    k_wprep8<<<wg, 256>>>(p);

    // shared first aggregation: A'_0 = x*dinv (fp16); AG0 packed (K=128)
    k_scale0<<<(NN * 32 + 255) / 256, 256>>>(x);
    k_gather_split<<<NN, 64>>>(128, 128, 0, 256);

    // e tower -> out[0 : NN*256]
    run_tower(be, Ke, Ce, offE, out, 256);
    // v tower -> out[NN*256 : NN*256 + NN*128]
    run_tower(bn, Kn, Cn, offN, out + (size_t)NN * 256, 128);
}

// round 16
// speedup vs baseline: 1.6899x; 1.0843x over previous
#include <cuda_runtime.h>
#include <cuda_fp16.h>
#include <cuda_bf16.h>
#include <math.h>
#include <stdint.h>

#define NN 50000
#define NE 400000
#define NBLK 391                 // ceil(50000/128)

// ---------------- scratch (device globals; allocation-free) ----------------
// packed bf16 operand layout: per row, per k-group of 16, quad (16B = 8 bf16):
// {hi(2tg),hi(2tg+1), hi(2tg+8),hi(2tg+9), lo(2tg),lo(2tg+1), lo(2tg+8),lo(2tg+9)}
__device__ __align__(16) __nv_bfloat16 g_apk_e[NN * 448]; // packed AG, e tower
__device__ __align__(16) __nv_bfloat16 g_apk_v[NN * 256]; // packed AG, v tower
__device__ __align__(16) __nv_bfloat16 g_ag0[NN * 256];   // packed shared AG0
__device__ __align__(16) __half        g_acte[NN * 256];  // e activations (fp16)
__device__ __align__(16) __half        g_actv[NN * 256];  // v activations (fp16)
__device__ __align__(16) __nv_bfloat16 g_wt[468992];      // packed W^T, 8 layers
__device__ float g_dinv[NN];
__device__ int   g_deg[NN];
__device__ int2  g_edges[NE];
__device__ int   g_rowptr[NN + 1];
__device__ int   g_cursor[NN];
__device__ int   g_col[NE];
__device__ int   g_is64;

// ---------------- helpers ----------------
__device__ __forceinline__ void mma16(float* c, const uint32_t* a, const uint32_t* b) {
    asm volatile(
        "mma.sync.aligned.m16n8k16.row.col.f32.bf16.bf16.f32 "
        "{%0,%1,%2,%3}, {%4,%5,%6,%7}, {%8,%9}, {%0,%1,%2,%3};"
        : "+f"(c[0]), "+f"(c[1]), "+f"(c[2]), "+f"(c[3])
        : "r"(a[0]), "r"(a[1]), "r"(a[2]), "r"(a[3]), "r"(b[0]), "r"(b[1]));
}
__device__ __forceinline__ void cpa16(uint32_t s, const void* g) {
    asm volatile("cp.async.ca.shared.global [%0], [%1], 16;" :: "r"(s), "l"(g));
}
#define CP_COMMIT() asm volatile("cp.async.commit_group;" ::: "memory")
#define CP_WAIT1()  asm volatile("cp.async.wait_group 1;" ::: "memory")

__device__ __forceinline__ void acc8h(float* s, const uint4& u) {
    float2 f;
    f = __half22float2(*(const __half2*)&u.x); s[0] += f.x; s[1] += f.y;
    f = __half22float2(*(const __half2*)&u.y); s[2] += f.x; s[3] += f.y;
    f = __half22float2(*(const __half2*)&u.z); s[4] += f.x; s[5] += f.y;
    f = __half22float2(*(const __half2*)&u.w); s[6] += f.x; s[7] += f.y;
}

// ---------------- edge dtype sniff + decode ----------------
__global__ void k_detect(const int* __restrict__ e) {
    int all0 = 1;
    for (int i = 0; i < 128; i++)
        if (e[2 * i + 1] != 0) { all0 = 0; break; }
    g_is64 = all0;
}

__global__ void k_prep(const int* __restrict__ e) {
    int i = blockIdx.x * 256 + threadIdx.x;
    if (i >= NE) return;
    int s, d;
    if (g_is64) { s = e[2 * i]; d = e[2 * (NE + i)]; }
    else        { s = e[i];     d = e[NE + i]; }
    s = min(max(s, 0), NN - 1);
    d = min(max(d, 0), NN - 1);
    g_edges[i] = make_int2(s, d);
}

// ---------------- degree / dinv / CSR build ----------------
__global__ void k_zero_deg() {
    int i = blockIdx.x * 256 + threadIdx.x;
    if (i < NN) g_deg[i] = 0;
}
__global__ void k_deg() {
    int i = blockIdx.x * 256 + threadIdx.x;
    if (i < NE) atomicAdd(&g_deg[g_edges[i].y], 1);
}
__global__ void k_dinv() {
    int i = blockIdx.x * 256 + threadIdx.x;
    if (i < NN) g_dinv[i] = rsqrtf((float)(g_deg[i] + 1));
}

__global__ __launch_bounds__(1024) void k_scan() {
    __shared__ int ssum[1024];
    const int t = threadIdx.x;
    const int CH = (NN + 1023) / 1024;
    int beg = t * CH;
    int end = min(beg + CH, NN);
    int s = 0;
    for (int i = beg; i < end; i++) s += g_deg[i];
    ssum[t] = s;
    __syncthreads();
    for (int off = 1; off < 1024; off <<= 1) {
        int v = ssum[t];
        int u = (t >= off) ? ssum[t - off] : 0;
        __syncthreads();
        ssum[t] = v + u;
        __syncthreads();
    }
    int run = (t == 0) ? 0 : ssum[t - 1];
    for (int i = beg; i < end; i++) {
        g_rowptr[i] = run;
        g_cursor[i] = run;
        run += g_deg[i];
    }
    if (t == 1023) g_rowptr[NN] = run;
}

__global__ void k_place() {
    int i = blockIdx.x * 256 + threadIdx.x;
    if (i >= NE) return;
    int2 sd = g_edges[i];
    int pos = atomicAdd(&g_cursor[sd.y], 1);
    g_col[pos] = sd.x;
}

// -------- A'_0 = x * dinv (fp16 into g_acte, stride 256) --------------------
__global__ void k_scale0(const float* __restrict__ x) {
    int i = blockIdx.x * 256 + threadIdx.x;      // quad index
    if (i >= NN * 32) return;
    int n = i >> 5, q = (i & 31) << 2;
    float dv = g_dinv[n];
    float4 v = *(const float4*)(x + (size_t)n * 128 + q);
    __half2 h0 = __floats2half2_rn(v.x * dv, v.y * dv);
    __half2 h1 = __floats2half2_rn(v.z * dv, v.w * dv);
    uint2 u;
    u.x = *(uint32_t*)&h0;
    u.y = *(uint32_t*)&h1;
    *(uint2*)(g_acte + (size_t)n * 256 + q) = u;
}

// -------- all-layer W prep: transpose + bf16 hi/lo split, packed ------------
struct WP8 {
    const float* W[8];
    int K[8], C[8], Kpad[8], Np[8], off[8];   // off = packed bf16 offset
};
__global__ void k_wprep8(WP8 p) {
    int l = blockIdx.y;
    int i = blockIdx.x * 256 + threadIdx.x;
    if (i >= p.Np[l] * p.Kpad[l]) return;
    int n = i / p.Kpad[l], k = i % p.Kpad[l];
    float w = (n < p.C[l] && k < p.K[l]) ? p.W[l][(size_t)k * p.C[l] + n] : 0.f;
    __nv_bfloat16 hi = __float2bfloat16_rn(w);
    __nv_bfloat16 lo = __float2bfloat16_rn(w - __bfloat162float(hi));
    int kg = k >> 4, pp = k & 15, pair = pp >> 1, elem = pp & 1;
    int tg = pair & 3, sec = pair >> 2;
    int base = p.off[l] + n * 2 * p.Kpad[l] + kg * 32 + tg * 8 + sec * 2 + elem;
    g_wt[base]     = hi;
    g_wt[base + 4] = lo;
}

// -------- packed bf16-split write helper (8 consecutive channels) ----------
__device__ __forceinline__ void pack_write8(__nv_bfloat16* dst, int rowbase,
                                            int c8, const float* val) {
    int kg = c8 >> 4, sec = (c8 >> 3) & 1;
    int base = rowbase + kg * 32 + sec * 2;
#pragma unroll
    for (int p = 0; p < 4; p++) {      // p == tg
        float v0 = val[2 * p], v1 = val[2 * p + 1];
        __nv_bfloat16 h0 = __float2bfloat16_rn(v0);
        __nv_bfloat16 h1 = __float2bfloat16_rn(v1);
        __nv_bfloat16 l0 = __float2bfloat16_rn(v0 - __bfloat162float(h0));
        __nv_bfloat16 l1 = __float2bfloat16_rn(v1 - __bfloat162float(h1));
        __nv_bfloat162 hh; hh.x = h0; hh.y = h1;
        __nv_bfloat162 ll; ll.x = l0; ll.y = l1;
        *(__nv_bfloat162*)(dst + base + p * 8)     = hh;
        *(__nv_bfloat162*)(dst + base + p * 8 + 4) = ll;
    }
}

// -------- AG0 gather (shared by both towers): g_acte[0:128] -> g_ag0 --------
// block 32 thr, 1 node; thread = 8 channels (one uint4 load per neighbor).
__global__ __launch_bounds__(32) void k_gather0()
{
    __shared__ int scol[32];
    const int d = blockIdx.x;
    const int beg = g_rowptr[d];
    const int deg = g_rowptr[d + 1] - beg;
    const int t = threadIdx.x & 15;          // 16 active threads cover 128 ch
    const bool act = threadIdx.x < 16;
    const int c8 = t << 3;

    float s[8];
#pragma unroll
    for (int j = 0; j < 8; j++) s[j] = 0.f;

    for (int done = 0; done < deg; done += 32) {
        int chunk = min(deg - done, 32);
        if (threadIdx.x < chunk) scol[threadIdx.x] = g_col[beg + done + threadIdx.x];
        __syncwarp();
        if (act)
            for (int i = 0; i < chunk; i++)
                acc8h(s, *(const uint4*)(g_acte + (size_t)scol[i] * 256 + c8));
        __syncwarp();
    }
    if (!act) return;
    const float dv = g_dinv[d];
    float self[8];
#pragma unroll
    for (int j = 0; j < 8; j++) self[j] = 0.f;
    acc8h(self, *(const uint4*)(g_acte + (size_t)d * 256 + c8));
    float val[8];
#pragma unroll
    for (int j = 0; j < 8; j++) val[j] = (s[j] + self[j]) * dv;
    pack_write8(g_ag0, d * 256, c8, val);
}

// -------- fused dual-tower gather: g_acte/g_actv -> g_apk_e/g_apk_v ---------
// block 64 thr, 1 node. threads [0,nE): e channels; [nE, nE+16): v channels.
// No channel guards: sources are zero-filled up to Npad64 >= KpadE.
__global__ __launch_bounds__(64) void k_gather_fused(int KpadE, int rowlenE)
{
    __shared__ int scol[64];
    const int d = blockIdx.x;
    const int beg = g_rowptr[d];
    const int deg = g_rowptr[d + 1] - beg;
    const int t = threadIdx.x;
    const int nE = KpadE >> 3;
    const bool isE = t < nE;
    const bool act = t < nE + 16;
    const int c8 = (isE ? t : t - nE) << 3;
    const __half* src = isE ? g_acte : g_actv;

    float s[8];
#pragma unroll
    for (int j = 0; j < 8; j++) s[j] = 0.f;

    for (int done = 0; done < deg; done += 64) {
        int chunk = min(deg - done, 64);
        if (t < chunk) scol[t] = g_col[beg + done + t];
        __syncthreads();
        if (act)
            for (int i = 0; i < chunk; i++)
                acc8h(s, *(const uint4*)(src + (size_t)scol[i] * 256 + c8));
        __syncthreads();
    }
    if (!act) return;
    const float dv = g_dinv[d];
    float self[8];
#pragma unroll
    for (int j = 0; j < 8; j++) self[j] = 0.f;
    acc8h(self, *(const uint4*)(src + (size_t)d * 256 + c8));
    float val[8];
#pragma unroll
    for (int j = 0; j < 8; j++) val[j] = (s[j] + self[j]) * dv;
    if (isE) pack_write8(g_apk_e, d * rowlenE, c8, val);
    else     pack_write8(g_apk_v, d * 256,     c8, val);
}

// -------- cp.async double-buffered bf16x3 GEMM, packed fragments ------------
// tile 128 x 64 x 32; 8 warps (4M x 2N). smem stage: A 128 rows x 192B @0,
// B 64 rows x 192B @24576; stage 36864B.
// aTag: 0=g_ag0, 1=g_apk_e, 2=g_apk_v. outSel: 0=g_acte, 1=g_actv, 2=ext sigm.
#define STG_B 36864
#define SMEM_TC (2 * STG_B)

__global__ __launch_bounds__(256) void k_gemm_tc(
    int woff, int aTag, int ldaH, int Kpad, int C,
    const float* __restrict__ bias, float* __restrict__ extOut,
    int outSel, int ldo)
{
    extern __shared__ char smc[];
    const int tid = threadIdx.x;
    const int wid = tid >> 5, lid = tid & 31;
    const int warpM = wid & 3, warpN = wid >> 2;
    const int g = lid >> 2, tg = lid & 3;
    const int row0 = blockIdx.y * 128;
    const int col0 = blockIdx.x * 64;
    const uint32_t sb = (uint32_t)__cvta_generic_to_shared(smc);
    const int ldbH = 2 * Kpad;

    const __nv_bfloat16* Abase = (aTag == 0) ? g_ag0
                               : (aTag == 1) ? g_apk_e : g_apk_v;

    const __nv_bfloat16* aSrc[4]; uint32_t aDst[4];
    const __nv_bfloat16* bSrc[2]; uint32_t bDst[2];
#pragma unroll
    for (int i = 0; i < 4; i++) {
        int l = tid + i * 256;          // 0..1023 : (row, quad j of 8)
        int r = l >> 3, j = l & 7;
        int gr = row0 + r; if (gr > NN - 1) gr = NN - 1;
        aSrc[i] = Abase + (size_t)gr * ldaH + j * 8;
        aDst[i] = (uint32_t)(r * 192 + j * 16);
    }
#pragma unroll
    for (int i = 0; i < 2; i++) {
        int l = tid + i * 256;          // 0..511
        int r = l >> 3, j = l & 7;
        bSrc[i] = g_wt + woff + (size_t)(col0 + r) * ldbH + j * 8;
        bDst[i] = (uint32_t)(24576 + r * 192 + j * 16);
    }

    float acc[2][4][4];
#pragma unroll
    for (int mt = 0; mt < 2; mt++)
#pragma unroll
        for (int nt = 0; nt < 4; nt++)
#pragma unroll
            for (int j = 0; j < 4; j++) acc[mt][nt][j] = 0.f;

    const int nch = Kpad >> 5;
#pragma unroll
    for (int i = 0; i < 4; i++) cpa16(sb + aDst[i], aSrc[i]);
#pragma unroll
    for (int i = 0; i < 2; i++) cpa16(sb + bDst[i], bSrc[i]);
    CP_COMMIT();

    for (int ch = 0; ch < nch; ch++) {
        if (ch + 1 < nch) {
            const uint32_t nOff = (uint32_t)((ch + 1) & 1) * STG_B;
            const int kt = (ch + 1) * 64;
#pragma unroll
            for (int i = 0; i < 4; i++) cpa16(sb + nOff + aDst[i], aSrc[i] + kt);
#pragma unroll
            for (int i = 0; i < 2; i++) cpa16(sb + nOff + bDst[i], bSrc[i] + kt);
        }
        CP_COMMIT();
        CP_WAIT1();
        __syncthreads();

        const char* st = smc + (ch & 1) * STG_B;

#pragma unroll
        for (int ks = 0; ks < 2; ks++) {
            const int colo = ks * 64 + tg * 16;
            uint32_t ah[2][4], al[2][4], bh[4][2], bl[4][2];
#pragma unroll
            for (int mt = 0; mt < 2; mt++) {
                int rA = warpM * 32 + mt * 16 + g;
                uint4 qg  = *(const uint4*)(st + rA * 192 + colo);
                uint4 qg8 = *(const uint4*)(st + (rA + 8) * 192 + colo);
                ah[mt][0] = qg.x;  ah[mt][1] = qg8.x;
                ah[mt][2] = qg.y;  ah[mt][3] = qg8.y;
                al[mt][0] = qg.z;  al[mt][1] = qg8.z;
                al[mt][2] = qg.w;  al[mt][3] = qg8.w;
            }
#pragma unroll
            for (int nt = 0; nt < 4; nt++) {
                int rB = warpN * 32 + nt * 8 + g;
                uint4 qb = *(const uint4*)(st + 24576 + rB * 192 + colo);
                bh[nt][0] = qb.x;  bh[nt][1] = qb.y;
                bl[nt][0] = qb.z;  bl[nt][1] = qb.w;
            }
#pragma unroll
            for (int mt = 0; mt < 2; mt++)
#pragma unroll
                for (int nt = 0; nt < 4; nt++) {
                    mma16(acc[mt][nt], ah[mt], bh[nt]);
                    mma16(acc[mt][nt], ah[mt], bl[nt]);
                    mma16(acc[mt][nt], al[mt], bh[nt]);
                }
        }
        __syncthreads();
    }

    __half* actOut = (outSel == 0) ? g_acte : g_actv;

    // epilogue: +bias, activation, (dinv), store
#pragma unroll
    for (int mt = 0; mt < 2; mt++) {
#pragma unroll
        for (int half = 0; half < 2; half++) {
            int r = row0 + warpM * 32 + mt * 16 + g + half * 8;
            if (r >= NN) continue;
            float dv = g_dinv[r];
#pragma unroll
            for (int nt = 0; nt < 4; nt++) {
                int c = col0 + warpN * 32 + nt * 8 + tg * 2;
                float v0 = (c < C)     ? acc[mt][nt][half * 2 + 0] + bias[c]     : 0.f;
                float v1 = (c + 1 < C) ? acc[mt][nt][half * 2 + 1] + bias[c + 1] : 0.f;
                if (outSel < 2) {
                    v0 = (c < C)     ? fmaxf(v0, 0.f) * dv : 0.f;
                    v1 = (c + 1 < C) ? fmaxf(v1, 0.f) * dv : 0.f;
                    *(__half2*)(actOut + (size_t)r * 256 + c) = __floats2half2_rn(v0, v1);
                } else {
                    if (c < C)
                        extOut[(size_t)r * ldo + c] = 1.f / (1.f + expf(-v0));
                    if (c + 1 < C)
                        extOut[(size_t)r * ldo + c + 1] = 1.f / (1.f + expf(-v1));
                }
            }
        }
    }
}

// ---------------------------------------------------------------------------
extern "C" void kernel_launch(void* const* d_in, const int* in_sizes, int n_in,
                              void* d_out, int out_size)
{
    const float* x = (const float*)d_in[0];
    const int* ei = (const int*)d_in[1];

    const float* We[4] = {(const float*)d_in[2], (const float*)d_in[4],
                          (const float*)d_in[6], (const float*)d_in[8]};
    const float* be[4] = {(const float*)d_in[3], (const float*)d_in[5],
                          (const float*)d_in[7], (const float*)d_in[9]};
    const float* Wn[4] = {(const float*)d_in[10], (const float*)d_in[12],
                          (const float*)d_in[14], (const float*)d_in[16]};
    const float* bn[4] = {(const float*)d_in[11], (const float*)d_in[13],
                          (const float*)d_in[15], (const float*)d_in[17]};

    float* out = (float*)d_out;

    cudaFuncSetAttribute(k_gemm_tc, cudaFuncAttributeMaxDynamicSharedMemorySize,
                         SMEM_TC);

    static const int Ke[4] = {128, 166, 192, 218};
    static const int Ce[4] = {166, 192, 218, 256};
    static const int Kn[4] = {128, 128, 128, 128};
    static const int Cn[4] = {128, 128, 128, 128};

    // combined W-prep descriptor (layers: e0..e3, v0..v3); packed bf16 offsets
    WP8 p;
    int offE[4], offN[4];
    int off = 0, maxElems = 0;
    for (int l = 0; l < 8; l++) {
        int K = (l < 4) ? Ke[l] : Kn[l - 4];
        int C = (l < 4) ? Ce[l] : Cn[l - 4];
        p.W[l] = (l < 4) ? We[l] : Wn[l - 4];
        p.K[l] = K; p.C[l] = C;
        p.Kpad[l] = (K + 31) & ~31;
        p.Np[l]   = (C + 63) & ~63;
        p.off[l]  = off;
        if (l < 4) offE[l] = off; else offN[l - 4] = off;
        int elems = p.Kpad[l] * p.Np[l];
        if (elems > maxElems) maxElems = elems;
        off += 2 * elems;                     // hi+lo packed together
    }
    // off = 466944 <= 468992

    // edge decode + graph normalization + CSR (shared by both towers)
    k_detect<<<1, 1>>>(ei);
    k_prep<<<(NE + 255) / 256, 256>>>(ei);
    k_zero_deg<<<(NN + 255) / 256, 256>>>();
    k_deg<<<(NE + 255) / 256, 256>>>();
    k_dinv<<<(NN + 255) / 256, 256>>>();
    k_scan<<<1, 1024>>>();
    k_place<<<(NE + 255) / 256, 256>>>();

    dim3 wg((maxElems + 255) / 256, 8);
    k_wprep8<<<wg, 256>>>(p);

    // shared first aggregation: A'_0 = x*dinv (fp16, in g_acte); AG0 packed
    k_scale0<<<(NN * 32 + 255) / 256, 256>>>(x);
    k_gather0<<<NN, 32>>>();

    // layer 0: both towers read AG0
    {
        dim3 ge(p.Np[0] / 64, NBLK);
        k_gemm_tc<<<ge, 256, SMEM_TC>>>(offE[0], 0, 256, 128, Ce[0],
                                        be[0], nullptr, 0, 0);
        dim3 gv(p.Np[4] / 64, NBLK);
        k_gemm_tc<<<gv, 256, SMEM_TC>>>(offN[0], 0, 256, 128, Cn[0],
                                        bn[0], nullptr, 1, 0);
    }

    // layers 1..3: fused gather, then both GEMMs
    for (int l = 1; l < 4; l++) {
        int KpadE = (Ke[l] + 31) & ~31;        // 192, 192, 224
        k_gather_fused<<<NN, 64>>>(KpadE, 2 * KpadE);

        dim3 ge(p.Np[l] / 64, NBLK);
        if (l < 3)
            k_gemm_tc<<<ge, 256, SMEM_TC>>>(offE[l], 1, 2 * KpadE, KpadE, Ce[l],
                                            be[l], nullptr, 0, 0);
        else
            k_gemm_tc<<<ge, 256, SMEM_TC>>>(offE[l], 1, 2 * KpadE, KpadE, Ce[l],
                                            be[l], out, 2, 256);

        dim3 gv(p.Np[4 + l] / 64, NBLK);
        if (l < 3)
            k_gemm_tc<<<gv, 256, SMEM_TC>>>(offN[l], 2, 256, 128, Cn[l],
                                            bn[l], nullptr, 1, 0);
        else
            k_gemm_tc<<<gv, 256, SMEM_TC>>>(offN[l], 2, 256, 128, Cn[l],
                                            bn[l], out + (size_t)NN * 256, 2, 128);
    }
}

// round 17
// speedup vs baseline: 1.9875x; 1.1761x over previous
#include <cuda_runtime.h>
#include <cuda_fp16.h>
#include <cuda_bf16.h>
#include <math.h>
#include <stdint.h>

#define NN 50000
#define NE 400000
#define NBLK 391                 // ceil(50000/128)

// ---------------- scratch (device globals; allocation-free) ----------------
// A packed (hi-only bf16): per row, per k16-group: 16 bf16 laid out as
// tg*4 + sec*2 + elem  (k = 2*tg + 8*sec + elem). Row length = Kpad bf16.
// B packed (hi/lo bf16): per row, per k16-group, 32 bf16 (R15 layout).
__device__ __align__(16) __nv_bfloat16 g_apk_e[NN * 224]; // packed AG, e tower
__device__ __align__(16) __nv_bfloat16 g_apk_v[NN * 128]; // packed AG, v tower
__device__ __align__(16) __nv_bfloat16 g_ag0[NN * 128];   // packed shared AG0
__device__ __align__(16) __half        g_acte[NN * 256];  // e activations (fp16)
__device__ __align__(16) __half        g_actv[NN * 256];  // v activations (fp16)
__device__ __align__(16) __nv_bfloat16 g_wt[468992];      // packed W^T (hi/lo)
__device__ float g_dinv[NN];
__device__ int   g_deg[NN];
__device__ int2  g_edges[NE];
__device__ int   g_rowptr[NN + 1];
__device__ int   g_cursor[NN];
__device__ int   g_col[NE];
__device__ int   g_is64;

// ---------------- helpers ----------------
__device__ __forceinline__ void mma16(float* c, const uint32_t* a, const uint32_t* b) {
    asm volatile(
        "mma.sync.aligned.m16n8k16.row.col.f32.bf16.bf16.f32 "
        "{%0,%1,%2,%3}, {%4,%5,%6,%7}, {%8,%9}, {%0,%1,%2,%3};"
        : "+f"(c[0]), "+f"(c[1]), "+f"(c[2]), "+f"(c[3])
        : "r"(a[0]), "r"(a[1]), "r"(a[2]), "r"(a[3]), "r"(b[0]), "r"(b[1]));
}
__device__ __forceinline__ void cpa16(uint32_t s, const void* g) {
    asm volatile("cp.async.ca.shared.global [%0], [%1], 16;" :: "r"(s), "l"(g));
}
#define CP_COMMIT() asm volatile("cp.async.commit_group;" ::: "memory")
#define CP_WAIT1()  asm volatile("cp.async.wait_group 1;" ::: "memory")

__device__ __forceinline__ void acc8h(float* s, const uint4& u) {
    float2 f;
    f = __half22float2(*(const __half2*)&u.x); s[0] += f.x; s[1] += f.y;
    f = __half22float2(*(const __half2*)&u.y); s[2] += f.x; s[3] += f.y;
    f = __half22float2(*(const __half2*)&u.z); s[4] += f.x; s[5] += f.y;
    f = __half22float2(*(const __half2*)&u.w); s[6] += f.x; s[7] += f.y;
}

// ---------------- edge dtype sniff + decode ----------------
__global__ void k_detect(const int* __restrict__ e) {
    int all0 = 1;
    for (int i = 0; i < 128; i++)
        if (e[2 * i + 1] != 0) { all0 = 0; break; }
    g_is64 = all0;
}

__global__ void k_prep(const int* __restrict__ e) {
    int i = blockIdx.x * 256 + threadIdx.x;
    if (i >= NE) return;
    int s, d;
    if (g_is64) { s = e[2 * i]; d = e[2 * (NE + i)]; }
    else        { s = e[i];     d = e[NE + i]; }
    s = min(max(s, 0), NN - 1);
    d = min(max(d, 0), NN - 1);
    g_edges[i] = make_int2(s, d);
}

// ---------------- degree / dinv / CSR build ----------------
__global__ void k_zero_deg() {
    int i = blockIdx.x * 256 + threadIdx.x;
    if (i < NN) g_deg[i] = 0;
}
__global__ void k_deg() {
    int i = blockIdx.x * 256 + threadIdx.x;
    if (i < NE) atomicAdd(&g_deg[g_edges[i].y], 1);
}
__global__ void k_dinv() {
    int i = blockIdx.x * 256 + threadIdx.x;
    if (i < NN) g_dinv[i] = rsqrtf((float)(g_deg[i] + 1));
}

__global__ __launch_bounds__(1024) void k_scan() {
    __shared__ int ssum[1024];
    const int t = threadIdx.x;
    const int CH = (NN + 1023) / 1024;
    int beg = t * CH;
    int end = min(beg + CH, NN);
    int s = 0;
    for (int i = beg; i < end; i++) s += g_deg[i];
    ssum[t] = s;
    __syncthreads();
    for (int off = 1; off < 1024; off <<= 1) {
        int v = ssum[t];
        int u = (t >= off) ? ssum[t - off] : 0;
        __syncthreads();
        ssum[t] = v + u;
        __syncthreads();
    }
    int run = (t == 0) ? 0 : ssum[t - 1];
    for (int i = beg; i < end; i++) {
        g_rowptr[i] = run;
        g_cursor[i] = run;
        run += g_deg[i];
    }
    if (t == 1023) g_rowptr[NN] = run;
}

__global__ void k_place() {
    int i = blockIdx.x * 256 + threadIdx.x;
    if (i >= NE) return;
    int2 sd = g_edges[i];
    int pos = atomicAdd(&g_cursor[sd.y], 1);
    g_col[pos] = sd.x;
}

// -------- A'_0 = x * dinv (fp16 into g_acte, stride 256) --------------------
__global__ void k_scale0(const float* __restrict__ x) {
    int i = blockIdx.x * 256 + threadIdx.x;      // quad index
    if (i >= NN * 32) return;
    int n = i >> 5, q = (i & 31) << 2;
    float dv = g_dinv[n];
    float4 v = *(const float4*)(x + (size_t)n * 128 + q);
    __half2 h0 = __floats2half2_rn(v.x * dv, v.y * dv);
    __half2 h1 = __floats2half2_rn(v.z * dv, v.w * dv);
    uint2 u;
    u.x = *(uint32_t*)&h0;
    u.y = *(uint32_t*)&h1;
    *(uint2*)(g_acte + (size_t)n * 256 + q) = u;
}

// -------- all-layer W prep: transpose + bf16 hi/lo split, packed ------------
struct WP8 {
    const float* W[8];
    int K[8], C[8], Kpad[8], Np[8], off[8];   // off = packed bf16 offset
};
__global__ void k_wprep8(WP8 p) {
    int l = blockIdx.y;
    int i = blockIdx.x * 256 + threadIdx.x;
    if (i >= p.Np[l] * p.Kpad[l]) return;
    int n = i / p.Kpad[l], k = i % p.Kpad[l];
    float w = (n < p.C[l] && k < p.K[l]) ? p.W[l][(size_t)k * p.C[l] + n] : 0.f;
    __nv_bfloat16 hi = __float2bfloat16_rn(w);
    __nv_bfloat16 lo = __float2bfloat16_rn(w - __bfloat162float(hi));
    int kg = k >> 4, pp = k & 15, pair = pp >> 1, elem = pp & 1;
    int tg = pair & 3, sec = pair >> 2;
    int base = p.off[l] + n * 2 * p.Kpad[l] + kg * 32 + tg * 8 + sec * 2 + elem;
    g_wt[base]     = hi;
    g_wt[base + 4] = lo;
}

// -------- packed hi-only write (8 consecutive channels) ---------------------
__device__ __forceinline__ void pack_write8(__nv_bfloat16* dst, int rowbase,
                                            int c8, const float* val) {
    int kg = c8 >> 4, sec = (c8 >> 3) & 1;
    int base = rowbase + kg * 16 + sec * 2;
#pragma unroll
    for (int p = 0; p < 4; p++) {      // p == tg, channels c8+2p, c8+2p+1
        __nv_bfloat162 hh;
        hh.x = __float2bfloat16_rn(val[2 * p]);
        hh.y = __float2bfloat16_rn(val[2 * p + 1]);
        *(__nv_bfloat162*)(dst + base + p * 4) = hh;
    }
}

// -------- AG0 gather (shared): g_acte[0:128] -> g_ag0 (rowlen 128) ----------
__global__ __launch_bounds__(32) void k_gather0()
{
    __shared__ int scol[32];
    const int d = blockIdx.x;
    const int beg = g_rowptr[d];
    const int deg = g_rowptr[d + 1] - beg;
    const int t = threadIdx.x & 15;
    const bool act = threadIdx.x < 16;
    const int c8 = t << 3;

    float s[8];
#pragma unroll
    for (int j = 0; j < 8; j++) s[j] = 0.f;

    for (int done = 0; done < deg; done += 32) {
        int chunk = min(deg - done, 32);
        if (threadIdx.x < chunk) scol[threadIdx.x] = g_col[beg + done + threadIdx.x];
        __syncwarp();
        if (act)
            for (int i = 0; i < chunk; i++)
                acc8h(s, *(const uint4*)(g_acte + (size_t)scol[i] * 256 + c8));
        __syncwarp();
    }
    if (!act) return;
    const float dv = g_dinv[d];
    float self[8];
#pragma unroll
    for (int j = 0; j < 8; j++) self[j] = 0.f;
    acc8h(self, *(const uint4*)(g_acte + (size_t)d * 256 + c8));
    float val[8];
#pragma unroll
    for (int j = 0; j < 8; j++) val[j] = (s[j] + self[j]) * dv;
    pack_write8(g_ag0, d * 128, c8, val);
}

// -------- fused dual-tower gather -> g_apk_e (rowlen KpadE) / g_apk_v -------
__global__ __launch_bounds__(64) void k_gather_fused(int KpadE)
{
    __shared__ int scol[64];
    const int d = blockIdx.x;
    const int beg = g_rowptr[d];
    const int deg = g_rowptr[d + 1] - beg;
    const int t = threadIdx.x;
    const int nE = KpadE >> 3;
    const bool isE = t < nE;
    const bool act = t < nE + 16;
    const int c8 = (isE ? t : t - nE) << 3;
    const __half* src = isE ? g_acte : g_actv;

    float s[8];
#pragma unroll
    for (int j = 0; j < 8; j++) s[j] = 0.f;

    for (int done = 0; done < deg; done += 64) {
        int chunk = min(deg - done, 64);
        if (t < chunk) scol[t] = g_col[beg + done + t];
        __syncthreads();
        if (act)
            for (int i = 0; i < chunk; i++)
                acc8h(s, *(const uint4*)(src + (size_t)scol[i] * 256 + c8));
        __syncthreads();
    }
    if (!act) return;
    const float dv = g_dinv[d];
    float self[8];
#pragma unroll
    for (int j = 0; j < 8; j++) self[j] = 0.f;
    acc8h(self, *(const uint4*)(src + (size_t)d * 256 + c8));
    float val[8];
#pragma unroll
    for (int j = 0; j < 8; j++) val[j] = (s[j] + self[j]) * dv;
    if (isE) pack_write8(g_apk_e, d * KpadE, c8, val);
    else     pack_write8(g_apk_v, d * 128,  c8, val);
}

// -------- fused dual-tower bf16x2 GEMM (A hi-only, W hi/lo) -----------------
// tile 128 x 64 x 32; 8 warps (4M x 2N).
// smem stage: A 128 rows x 96B (64 data) @0; B 64 rows x 192B @12288; 24576B.
#define STG_B 24576
#define SMEM_TC (2 * STG_B)

struct GP {
    int woff, aTag, ldaH, Kpad, C, outSel, ldo;   // outSel: 0=acte,1=actv,2=ext
    const float* bias;
    float* extOut;
};

__global__ __launch_bounds__(256) void k_gemm2(GP pe, GP pv, int nxE)
{
    extern __shared__ char smc[];
    const bool isE = (int)blockIdx.x < nxE;
    const int woff = isE ? pe.woff : pv.woff;
    const int aTag = isE ? pe.aTag : pv.aTag;
    const int ldaH = isE ? pe.ldaH : pv.ldaH;
    const int Kpad = isE ? pe.Kpad : pv.Kpad;
    const int C    = isE ? pe.C    : pv.C;
    const int outSel = isE ? pe.outSel : pv.outSel;
    const int ldo  = isE ? pe.ldo  : pv.ldo;
    const float* bias = isE ? pe.bias : pv.bias;
    float* extOut = isE ? pe.extOut : pv.extOut;

    const int tid = threadIdx.x;
    const int wid = tid >> 5, lid = tid & 31;
    const int warpM = wid & 3, warpN = wid >> 2;
    const int g = lid >> 2, tg = lid & 3;
    const int row0 = blockIdx.y * 128;
    const int col0 = (isE ? blockIdx.x : blockIdx.x - nxE) * 64;
    const uint32_t sb = (uint32_t)__cvta_generic_to_shared(smc);
    const int ldbH = 2 * Kpad;

    const __nv_bfloat16* Abase = (aTag == 0) ? g_ag0
                               : (aTag == 1) ? g_apk_e : g_apk_v;

    const __nv_bfloat16* aSrc[2]; uint32_t aDst[2];
    const __nv_bfloat16* bSrc[2]; uint32_t bDst[2];
#pragma unroll
    for (int i = 0; i < 2; i++) {
        int l = tid + i * 256;          // 0..511 : (row, quad j of 4)
        int r = l >> 2, j = l & 3;
        int gr = row0 + r; if (gr > NN - 1) gr = NN - 1;
        aSrc[i] = Abase + (size_t)gr * ldaH + j * 8;
        aDst[i] = (uint32_t)(r * 96 + j * 16);
    }
#pragma unroll
    for (int i = 0; i < 2; i++) {
        int l = tid + i * 256;          // 0..511 : (row, quad j of 8)
        int r = l >> 3, j = l & 7;
        bSrc[i] = g_wt + woff + (size_t)(col0 + r) * ldbH + j * 8;
        bDst[i] = (uint32_t)(12288 + r * 192 + j * 16);
    }

    float acc[2][4][4];
#pragma unroll
    for (int mt = 0; mt < 2; mt++)
#pragma unroll
        for (int nt = 0; nt < 4; nt++)
#pragma unroll
            for (int j = 0; j < 4; j++) acc[mt][nt][j] = 0.f;

    const int nch = Kpad >> 5;
#pragma unroll
    for (int i = 0; i < 2; i++) cpa16(sb + aDst[i], aSrc[i]);
#pragma unroll
    for (int i = 0; i < 2; i++) cpa16(sb + bDst[i], bSrc[i]);
    CP_COMMIT();

    for (int ch = 0; ch < nch; ch++) {
        if (ch + 1 < nch) {
            const uint32_t nOff = (uint32_t)((ch + 1) & 1) * STG_B;
            const int ktA = (ch + 1) * 32;   // halves per chunk (A)
            const int ktB = (ch + 1) * 64;   // halves per chunk (B)
#pragma unroll
            for (int i = 0; i < 2; i++) cpa16(sb + nOff + aDst[i], aSrc[i] + ktA);
#pragma unroll
            for (int i = 0; i < 2; i++) cpa16(sb + nOff + bDst[i], bSrc[i] + ktB);
        }
        CP_COMMIT();
        CP_WAIT1();
        __syncthreads();

        const char* st = smc + (ch & 1) * STG_B;

#pragma unroll
        for (int ks = 0; ks < 2; ks++) {
            uint32_t ah[2][4], bh[4][2], bl[4][2];
#pragma unroll
            for (int mt = 0; mt < 2; mt++) {
                int rA = warpM * 32 + mt * 16 + g;
                uint2 qg  = *(const uint2*)(st + rA * 96 + ks * 32 + tg * 8);
                uint2 qg8 = *(const uint2*)(st + (rA + 8) * 96 + ks * 32 + tg * 8);
                ah[mt][0] = qg.x;  ah[mt][1] = qg8.x;
                ah[mt][2] = qg.y;  ah[mt][3] = qg8.y;
            }
#pragma unroll
            for (int nt = 0; nt < 4; nt++) {
                int rB = warpN * 32 + nt * 8 + g;
                uint4 qb = *(const uint4*)(st + 12288 + rB * 192 + ks * 64 + tg * 16);
                bh[nt][0] = qb.x;  bh[nt][1] = qb.y;
                bl[nt][0] = qb.z;  bl[nt][1] = qb.w;
            }
#pragma unroll
            for (int mt = 0; mt < 2; mt++)
#pragma unroll
                for (int nt = 0; nt < 4; nt++) {
                    mma16(acc[mt][nt], ah[mt], bh[nt]);
                    mma16(acc[mt][nt], ah[mt], bl[nt]);
                }
        }
        __syncthreads();
    }

    __half* actOut = (outSel == 0) ? g_acte : g_actv;

    // epilogue: +bias, activation, (dinv), store
#pragma unroll
    for (int mt = 0; mt < 2; mt++) {
#pragma unroll
        for (int half = 0; half < 2; half++) {
            int r = row0 + warpM * 32 + mt * 16 + g + half * 8;
            if (r >= NN) continue;
            float dv = g_dinv[r];
#pragma unroll
            for (int nt = 0; nt < 4; nt++) {
                int c = col0 + warpN * 32 + nt * 8 + tg * 2;
                float v0 = (c < C)     ? acc[mt][nt][half * 2 + 0] + bias[c]     : 0.f;
                float v1 = (c + 1 < C) ? acc[mt][nt][half * 2 + 1] + bias[c + 1] : 0.f;
                if (outSel < 2) {
                    v0 = (c < C)     ? fmaxf(v0, 0.f) * dv : 0.f;
                    v1 = (c + 1 < C) ? fmaxf(v1, 0.f) * dv : 0.f;
                    *(__half2*)(actOut + (size_t)r * 256 + c) = __floats2half2_rn(v0, v1);
                } else {
                    if (c < C)
                        extOut[(size_t)r * ldo + c] = 1.f / (1.f + expf(-v0));
                    if (c + 1 < C)
                        extOut[(size_t)r * ldo + c + 1] = 1.f / (1.f + expf(-v1));
                }
            }
        }
    }
}

// ---------------------------------------------------------------------------
extern "C" void kernel_launch(void* const* d_in, const int* in_sizes, int n_in,
                              void* d_out, int out_size)
{
    const float* x = (const float*)d_in[0];
    const int* ei = (const int*)d_in[1];

    const float* We[4] = {(const float*)d_in[2], (const float*)d_in[4],
                          (const float*)d_in[6], (const float*)d_in[8]};
    const float* be[4] = {(const float*)d_in[3], (const float*)d_in[5],
                          (const float*)d_in[7], (const float*)d_in[9]};
    const float* Wn[4] = {(const float*)d_in[10], (const float*)d_in[12],
                          (const float*)d_in[14], (const float*)d_in[16]};
    const float* bn[4] = {(const float*)d_in[11], (const float*)d_in[13],
                          (const float*)d_in[15], (const float*)d_in[17]};

    float* out = (float*)d_out;

    cudaFuncSetAttribute(k_gemm2, cudaFuncAttributeMaxDynamicSharedMemorySize,
                         SMEM_TC);

    static const int Ke[4] = {128, 166, 192, 218};
    static const int Ce[4] = {166, 192, 218, 256};
    static const int Kn[4] = {128, 128, 128, 128};
    static const int Cn[4] = {128, 128, 128, 128};

    // combined W-prep descriptor (layers: e0..e3, v0..v3); packed bf16 offsets
    WP8 p;
    int offE[4], offN[4];
    int off = 0, maxElems = 0;
    for (int l = 0; l < 8; l++) {
        int K = (l < 4) ? Ke[l] : Kn[l - 4];
        int C = (l < 4) ? Ce[l] : Cn[l - 4];
        p.W[l] = (l < 4) ? We[l] : Wn[l - 4];
        p.K[l] = K; p.C[l] = C;
        p.Kpad[l] = (K + 31) & ~31;
        p.Np[l]   = (C + 63) & ~63;
        p.off[l]  = off;
        if (l < 4) offE[l] = off; else offN[l - 4] = off;
        int elems = p.Kpad[l] * p.Np[l];
        if (elems > maxElems) maxElems = elems;
        off += 2 * elems;                     // hi+lo packed together (B)
    }
    // off = 466944 <= 468992

    // edge decode + graph normalization + CSR (shared by both towers)
    k_detect<<<1, 1>>>(ei);
    k_prep<<<(NE + 255) / 256, 256>>>(ei);
    k_zero_deg<<<(NN + 255) / 256, 256>>>();
    k_deg<<<(NE + 255) / 256, 256>>>();
    k_dinv<<<(NN + 255) / 256, 256>>>();
    k_scan<<<1, 1024>>>();
    k_place<<<(NE + 255) / 256, 256>>>();

    dim3 wg((maxElems + 255) / 256, 8);
    k_wprep8<<<wg, 256>>>(p);

    // shared first aggregation: A'_0 = x*dinv (fp16, in g_acte); AG0 packed
    k_scale0<<<(NN * 32 + 255) / 256, 256>>>(x);
    k_gather0<<<NN, 32>>>();

    for (int l = 0; l < 4; l++) {
        int KpadE = (Ke[l] + 31) & ~31;        // 128, 192, 192, 224
        if (l > 0)
            k_gather_fused<<<NN, 64>>>(KpadE);

        GP pe, pv;
        pe.woff = offE[l];
        pe.aTag = (l == 0) ? 0 : 1;
        pe.ldaH = (l == 0) ? 128 : KpadE;
        pe.Kpad = KpadE;
        pe.C    = Ce[l];
        pe.outSel = (l == 3) ? 2 : 0;
        pe.ldo  = 256;
        pe.bias = be[l];
        pe.extOut = out;

        pv.woff = offN[l];
        pv.aTag = (l == 0) ? 0 : 2;
        pv.ldaH = 128;
        pv.Kpad = 128;
        pv.C    = Cn[l];
        pv.outSel = (l == 3) ? 2 : 1;
        pv.ldo  = 128;
        pv.bias = bn[l];
        pv.extOut = out + (size_t)NN * 256;

        int nxE = p.Np[l] / 64;
        int nxV = p.Np[4 + l] / 64;
        dim3 gg(nxE + nxV, NBLK);
        k_gemm2<<<gg, 256, SMEM_TC>>>(pe, pv, nxE);
    }
}